// round 1
// baseline (speedup 1.0000x reference)
#include <cuda_runtime.h>

#define BB 8
#define CC 256
#define NN 4096

// Scratch (device globals — no allocation allowed in kernel_launch)
__device__ float g_Q[BB * CC * NN];       // 32 MB
__device__ float g_K[BB * CC * NN];       // 32 MB
__device__ float g_V[BB * CC * NN];       // 32 MB
__device__ float g_ctx[2][BB * CC * CC];  // split-K partials, 2 x 2 MB
__device__ float g_Wc[BB * CC * CC];      // 2 MB

// ---------------------------------------------------------------------------
// Shared inner product: 64x64 C-tile, 16-deep K-slice, 256 threads, 4x4/thread
// As/Bs stored [k][m]/[k][n] padded to 68 for float4 reads.
// ---------------------------------------------------------------------------
#define MMA_STEP(As, Bs, tx, ty, acc)                                   \
    {                                                                   \
        _Pragma("unroll")                                               \
        for (int kk = 0; kk < 16; kk++) {                               \
            float4 a4 = *(const float4*)&As[kk][(ty) * 4];              \
            float4 b4 = *(const float4*)&Bs[kk][(tx) * 4];              \
            float av[4] = {a4.x, a4.y, a4.z, a4.w};                     \
            float bw[4] = {b4.x, b4.y, b4.z, b4.w};                     \
            _Pragma("unroll")                                           \
            for (int i = 0; i < 4; i++) {                               \
                _Pragma("unroll")                                       \
                for (int j = 0; j < 4; j++)                             \
                    acc[i][j] += av[i] * bw[j];                         \
            }                                                           \
        }                                                               \
    }

// ---------------------------------------------------------------------------
// Kernel 1: Q = wq @ x + bq  (tiles y=0..3)  and  KV = wkv @ cproj + bkv
// (tiles y=4..11; rows <256 -> K, rows >=256 -> V).
// grid (64, 12, 8), 256 threads
// ---------------------------------------------------------------------------
__global__ __launch_bounds__(256) void gemm_qkv(
    const float* __restrict__ x, const float* __restrict__ cp,
    const float* __restrict__ wq, const float* __restrict__ bq,
    const float* __restrict__ wkv, const float* __restrict__ bkv)
{
    __shared__ __align__(16) float As[16][68];
    __shared__ __align__(16) float Bs[16][68];

    const int b = blockIdx.z;
    const int nbase = blockIdx.x * 64;
    const int tyb = blockIdx.y;

    const float* W;
    const float* X;
    const float* bias;
    int mbase;
    if (tyb < 4) { W = wq;  X = x;  bias = bq;  mbase = tyb * 64; }
    else         { W = wkv; X = cp; bias = bkv; mbase = (tyb - 4) * 64; }

    const float* Aptr = W + mbase * CC;
    const float* Bptr = X + (size_t)b * CC * NN + nbase;

    const int t = threadIdx.x;
    const int tx = t & 15, ty = t >> 4;
    const int arow = t >> 4, acol = t & 15;   // A tile: 64x16
    const int bcol = t & 63, brow = t >> 6;   // B tile: 16x64

    float acc[4][4] = {};

    for (int k0 = 0; k0 < CC; k0 += 16) {
#pragma unroll
        for (int r = 0; r < 4; r++)
            As[acol][arow + 16 * r] = Aptr[(arow + 16 * r) * CC + k0 + acol];
#pragma unroll
        for (int r = 0; r < 4; r++)
            Bs[brow + 4 * r][bcol] = Bptr[(size_t)(k0 + brow + 4 * r) * NN + bcol];
        __syncthreads();
        MMA_STEP(As, Bs, tx, ty, acc)
        __syncthreads();
    }

#pragma unroll
    for (int i = 0; i < 4; i++) {
        const int grow = mbase + ty * 4 + i;
        const float bb = bias[grow];
        float4 v = make_float4(acc[i][0] + bb, acc[i][1] + bb,
                               acc[i][2] + bb, acc[i][3] + bb);
        float* Out;
        if (tyb < 4)          Out = g_Q + ((size_t)b * CC + grow) * NN;
        else if (grow < CC)   Out = g_K + ((size_t)b * CC + grow) * NN;
        else                  Out = g_V + ((size_t)b * CC + (grow - CC)) * NN;
        *(float4*)&Out[nbase + tx * 4] = v;
    }
}

// ---------------------------------------------------------------------------
// Kernel 2: softmax over N=4096 for each (b,c) row of K, in place.
// grid 2048, 256 threads; 16 values/thread in registers.
// ---------------------------------------------------------------------------
__global__ __launch_bounds__(256) void softmax_k_kernel()
{
    float* p = g_K + (size_t)blockIdx.x * NN;
    const int t = threadIdx.x;
    __shared__ float sh[8];

    float v[16];
    float m = -1e30f;
#pragma unroll
    for (int i = 0; i < 16; i++) { v[i] = p[t + 256 * i]; m = fmaxf(m, v[i]); }
#pragma unroll
    for (int o = 16; o; o >>= 1) m = fmaxf(m, __shfl_xor_sync(0xffffffffu, m, o));
    if ((t & 31) == 0) sh[t >> 5] = m;
    __syncthreads();
    m = sh[0];
#pragma unroll
    for (int i = 1; i < 8; i++) m = fmaxf(m, sh[i]);

    float s = 0.f;
#pragma unroll
    for (int i = 0; i < 16; i++) { v[i] = __expf(v[i] - m); s += v[i]; }
#pragma unroll
    for (int o = 16; o; o >>= 1) s += __shfl_xor_sync(0xffffffffu, s, o);
    __syncthreads();
    if ((t & 31) == 0) sh[t >> 5] = s;
    __syncthreads();
    s = 0.f;
#pragma unroll
    for (int i = 0; i < 8; i++) s += sh[i];

    const float inv = 1.f / s;
#pragma unroll
    for (int i = 0; i < 16; i++) p[t + 256 * i] = v[i] * inv;
}

// ---------------------------------------------------------------------------
// Kernel 3: softmax over d=64 (channel within head) of scale*Q, in place.
// One thread per (b,h,n); loads strided by N but coalesced across the warp.
// grid 512, 256 threads.
// ---------------------------------------------------------------------------
__global__ __launch_bounds__(256) void softmax_q_kernel()
{
    const int idx = blockIdx.x * 256 + threadIdx.x;  // 131072 = 8*4*4096
    const int n = idx & (NN - 1);
    const int bh = idx >> 12;                        // b*4 + h
    float* base = g_Q + (size_t)bh * 64 * NN + n;

    float m = -1e30f;
#pragma unroll 8
    for (int d = 0; d < 64; d++) m = fmaxf(m, base[d * NN]);
    float s = 0.f;
#pragma unroll 8
    for (int d = 0; d < 64; d++) s += __expf((base[d * NN] - m) * 0.25f);
    const float inv = 1.f / s;
#pragma unroll 8
    for (int d = 0; d < 64; d++) base[d * NN] = __expf((base[d * NN] - m) * 0.25f) * inv;
}

// ---------------------------------------------------------------------------
// Kernel 4: context[b][c][d] = sum_n k[b][c][n] * V[b][d][n]   (A @ B^T)
// split-K in 2 halves for parallelism; grid (4, 4, 16), 256 threads.
// ---------------------------------------------------------------------------
__global__ __launch_bounds__(256) void gemm_ctx()
{
    __shared__ __align__(16) float As[16][68];
    __shared__ __align__(16) float Bs[16][68];

    const int half = blockIdx.z & 1;
    const int b = blockIdx.z >> 1;
    const int mbase = blockIdx.y * 64;  // c tile
    const int nbase = blockIdx.x * 64;  // d tile
    const float* Ap = g_K + ((size_t)b * CC + mbase) * NN;
    const float* Bp = g_V + ((size_t)b * CC + nbase) * NN;

    const int t = threadIdx.x;
    const int tx = t & 15, ty = t >> 4;
    const int lrow = t >> 4, lcol = t & 15;

    float acc[4][4] = {};
    const int kstart = half * 2048;
    for (int k0 = kstart; k0 < kstart + 2048; k0 += 16) {
#pragma unroll
        for (int r = 0; r < 4; r++) {
            As[lcol][lrow + 16 * r] = Ap[(size_t)(lrow + 16 * r) * NN + k0 + lcol];
            Bs[lcol][lrow + 16 * r] = Bp[(size_t)(lrow + 16 * r) * NN + k0 + lcol];
        }
        __syncthreads();
        MMA_STEP(As, Bs, tx, ty, acc)
        __syncthreads();
    }

    float* Out = g_ctx[half] + ((size_t)b * CC + mbase) * CC + nbase;
#pragma unroll
    for (int i = 0; i < 4; i++) {
        float4 v = make_float4(acc[i][0], acc[i][1], acc[i][2], acc[i][3]);
        *(float4*)&Out[(ty * 4 + i) * CC + tx * 4] = v;
    }
}

// ---------------------------------------------------------------------------
// Kernel 5: Wc[b] = wo @ (ctx0[b] + ctx1[b]).   grid (4, 4, 8)
// ---------------------------------------------------------------------------
__global__ __launch_bounds__(256) void gemm_wc(const float* __restrict__ wo)
{
    __shared__ __align__(16) float As[16][68];
    __shared__ __align__(16) float Bs[16][68];

    const int b = blockIdx.z;
    const int mbase = blockIdx.y * 64;
    const int nbase = blockIdx.x * 64;
    const float* Aptr = wo + mbase * CC;
    const float* B0 = g_ctx[0] + (size_t)b * CC * CC + nbase;
    const float* B1 = g_ctx[1] + (size_t)b * CC * CC + nbase;

    const int t = threadIdx.x;
    const int tx = t & 15, ty = t >> 4;
    const int arow = t >> 4, acol = t & 15;
    const int bcol = t & 63, brow = t >> 6;

    float acc[4][4] = {};
    for (int k0 = 0; k0 < CC; k0 += 16) {
#pragma unroll
        for (int r = 0; r < 4; r++)
            As[acol][arow + 16 * r] = Aptr[(arow + 16 * r) * CC + k0 + acol];
#pragma unroll
        for (int r = 0; r < 4; r++) {
            const int kr = (k0 + brow + 4 * r) * CC + bcol;
            Bs[brow + 4 * r][bcol] = B0[kr] + B1[kr];
        }
        __syncthreads();
        MMA_STEP(As, Bs, tx, ty, acc)
        __syncthreads();
    }

    float* Out = g_Wc + ((size_t)b * CC + mbase) * CC + nbase;
#pragma unroll
    for (int i = 0; i < 4; i++) {
        float4 v = make_float4(acc[i][0], acc[i][1], acc[i][2], acc[i][3]);
        *(float4*)&Out[(ty * 4 + i) * CC + tx * 4] = v;
    }
}

// ---------------------------------------------------------------------------
// Kernel 6: out[b] = Wc[b] @ q[b] + bo.    grid (64, 4, 8)
// ---------------------------------------------------------------------------
__global__ __launch_bounds__(256) void gemm_out(const float* __restrict__ bo,
                                                float* __restrict__ out)
{
    __shared__ __align__(16) float As[16][68];
    __shared__ __align__(16) float Bs[16][68];

    const int b = blockIdx.z;
    const int mbase = blockIdx.y * 64;
    const int nbase = blockIdx.x * 64;
    const float* Aptr = g_Wc + (size_t)b * CC * CC + mbase * CC;
    const float* Bptr = g_Q + (size_t)b * CC * NN + nbase;

    const int t = threadIdx.x;
    const int tx = t & 15, ty = t >> 4;
    const int arow = t >> 4, acol = t & 15;
    const int bcol = t & 63, brow = t >> 6;

    float acc[4][4] = {};
    for (int k0 = 0; k0 < CC; k0 += 16) {
#pragma unroll
        for (int r = 0; r < 4; r++)
            As[acol][arow + 16 * r] = Aptr[(arow + 16 * r) * CC + k0 + acol];
#pragma unroll
        for (int r = 0; r < 4; r++)
            Bs[brow + 4 * r][bcol] = Bptr[(size_t)(k0 + brow + 4 * r) * NN + bcol];
        __syncthreads();
        MMA_STEP(As, Bs, tx, ty, acc)
        __syncthreads();
    }

#pragma unroll
    for (int i = 0; i < 4; i++) {
        const int grow = mbase + ty * 4 + i;
        const float bb = bo[grow];
        float4 v = make_float4(acc[i][0] + bb, acc[i][1] + bb,
                               acc[i][2] + bb, acc[i][3] + bb);
        *(float4*)&out[((size_t)b * CC + grow) * NN + nbase + tx * 4] = v;
    }
}

// ---------------------------------------------------------------------------
extern "C" void kernel_launch(void* const* d_in, const int* in_sizes, int n_in,
                              void* d_out, int out_size)
{
    const float* x    = (const float*)d_in[0];
    const float* cp   = (const float*)d_in[1];
    const float* wq   = (const float*)d_in[2];
    const float* bq   = (const float*)d_in[3];
    const float* wkv  = (const float*)d_in[4];
    const float* bkv  = (const float*)d_in[5];
    const float* wo   = (const float*)d_in[6];
    const float* bo   = (const float*)d_in[7];
    float* out = (float*)d_out;

    gemm_qkv<<<dim3(64, 12, 8), 256>>>(x, cp, wq, bq, wkv, bkv);
    softmax_k_kernel<<<2048, 256>>>();
    softmax_q_kernel<<<512, 256>>>();
    gemm_ctx<<<dim3(4, 4, 16), 256>>>();
    gemm_wc<<<dim3(4, 4, 8), 256>>>(wo);
    gemm_out<<<dim3(64, 4, 8), 256>>>(bo, out);
}

// round 2
// speedup vs baseline: 1.6640x; 1.6640x over previous
#include <cuda_runtime.h>
#include <cstdint>

#define BB 8
#define CC 256
#define NN 4096
#define NSPLIT 8

// Scratch (device globals — no allocation allowed)
__device__ __align__(128) float g_Q[BB * CC * NN];          // 32 MB
__device__ __align__(128) float g_K[BB * CC * NN];          // 32 MB
__device__ __align__(128) float g_V[BB * CC * NN];          // 32 MB
__device__ __align__(128) float g_ctx[NSPLIT][BB * CC * CC];// 16 MB split-K partials
__device__ __align__(128) float g_Wc[BB * CC * CC];         // 2 MB

// ---------------------------------------------------------------------------
// tf32 helpers
// ---------------------------------------------------------------------------
__device__ __forceinline__ uint32_t f2tf(float x) {
    uint32_t u;
    asm("cvt.rna.tf32.f32 %0, %1;" : "=r"(u) : "f"(x));
    return u;
}

__device__ __forceinline__ void mma8(float* c, const uint32_t* a, const uint32_t* b) {
    asm volatile(
        "mma.sync.aligned.m16n8k8.row.col.f32.tf32.tf32.f32 "
        "{%0,%1,%2,%3}, {%4,%5,%6,%7}, {%8,%9}, {%0,%1,%2,%3};"
        : "+f"(c[0]), "+f"(c[1]), "+f"(c[2]), "+f"(c[3])
        : "r"(a[0]), "r"(a[1]), "r"(a[2]), "r"(a[3]), "r"(b[0]), "r"(b[1]));
}

// ---------------------------------------------------------------------------
// Core tf32 tensor-core GEMM tile: C[128x128] += A[128xK] * B[KxN-tile]
// BCOL=false: B stored row-major [K][ldb] (contiguous in n)
// BCOL=true : B stored as B[n][ldb] with k contiguous (i.e. C = A * B^T)
// 256 threads, 8 warps (2x4), each warp 64x32 via 4x4 m16n8k8 tiles.
// ---------------------------------------------------------------------------
template <bool BCOL>
__device__ __forceinline__ void gemm_core_tf32(
    const float* __restrict__ Aptr, int lda,
    const float* __restrict__ Bptr, int ldb,
    int K, float acc[4][4][4])
{
    __shared__ __align__(16) float SA[2][128][20];
    __shared__ __align__(16) float SB[2][16][136];

    const int t = threadIdx.x;
    const int warp = t >> 5, lane = t & 31;
    const int wm = (warp >> 2) * 64, wn = (warp & 3) * 32;
    const int g = lane >> 2, tg = lane & 3;

    // loader indices
    const int arow = t >> 1, ahalf = (t & 1) * 8;       // A: row, 8 floats
    const int bk = t >> 5, bc = (t & 31) * 4;           // B row-major
    const int brn = t >> 1, bhalf = (t & 1) * 8;        // B col-major

    float4 ra0, ra1, rb0, rb1;

    auto loadg = [&](int k0) {
        const float* ap = Aptr + (size_t)arow * lda + k0 + ahalf;
        ra0 = *(const float4*)ap;
        ra1 = *(const float4*)(ap + 4);
        if (BCOL) {
            const float* bp = Bptr + (size_t)brn * ldb + k0 + bhalf;
            rb0 = *(const float4*)bp;
            rb1 = *(const float4*)(bp + 4);
        } else {
            const float* bp = Bptr + (size_t)(k0 + bk) * ldb + bc;
            rb0 = *(const float4*)bp;
            rb1 = *(const float4*)(bp + (size_t)8 * ldb);
        }
    };

    auto stores = [&](int buf) {
        float av[8] = {ra0.x, ra0.y, ra0.z, ra0.w, ra1.x, ra1.y, ra1.z, ra1.w};
#pragma unroll
        for (int c = 0; c < 8; c++)
            SA[buf][arow][ahalf + c] = __uint_as_float(f2tf(av[c]));
        if (BCOL) {
            float bv[8] = {rb0.x, rb0.y, rb0.z, rb0.w, rb1.x, rb1.y, rb1.z, rb1.w};
#pragma unroll
            for (int c = 0; c < 8; c++)
                SB[buf][bhalf + c][brn] = __uint_as_float(f2tf(bv[c]));
        } else {
            float4 v0 = make_float4(__uint_as_float(f2tf(rb0.x)), __uint_as_float(f2tf(rb0.y)),
                                    __uint_as_float(f2tf(rb0.z)), __uint_as_float(f2tf(rb0.w)));
            float4 v1 = make_float4(__uint_as_float(f2tf(rb1.x)), __uint_as_float(f2tf(rb1.y)),
                                    __uint_as_float(f2tf(rb1.z)), __uint_as_float(f2tf(rb1.w)));
            *(float4*)&SB[buf][bk][bc] = v0;
            *(float4*)&SB[buf][bk + 8][bc] = v1;
        }
    };

    auto compute = [&](int buf) {
#pragma unroll
        for (int s = 0; s < 2; s++) {
            uint32_t afr[4][4], bfr[4][2];
#pragma unroll
            for (int i = 0; i < 4; i++) {
                afr[i][0] = __float_as_uint(SA[buf][wm + 16 * i + g][8 * s + tg]);
                afr[i][1] = __float_as_uint(SA[buf][wm + 16 * i + g + 8][8 * s + tg]);
                afr[i][2] = __float_as_uint(SA[buf][wm + 16 * i + g][8 * s + tg + 4]);
                afr[i][3] = __float_as_uint(SA[buf][wm + 16 * i + g + 8][8 * s + tg + 4]);
            }
#pragma unroll
            for (int j = 0; j < 4; j++) {
                bfr[j][0] = __float_as_uint(SB[buf][8 * s + tg][wn + 8 * j + g]);
                bfr[j][1] = __float_as_uint(SB[buf][8 * s + tg + 4][wn + 8 * j + g]);
            }
#pragma unroll
            for (int i = 0; i < 4; i++)
#pragma unroll
                for (int j = 0; j < 4; j++)
                    mma8(acc[i][j], afr[i], bfr[j]);
        }
    };

    loadg(0);
    stores(0);
    __syncthreads();
    const int nIter = K / 16;
    for (int it = 0; it < nIter; ++it) {
        const int cur = it & 1;
        if (it + 1 < nIter) loadg(16 * (it + 1));
        compute(cur);
        if (it + 1 < nIter) stores(cur ^ 1);
        __syncthreads();
    }
}

// ---------------------------------------------------------------------------
// Kernel 1: Q = wq@x + bq (y=0..1), KV = wkv@cproj + bkv (y=2..5)
// grid (32, 6, 8), 256 threads
// ---------------------------------------------------------------------------
__global__ __launch_bounds__(256) void gemm_qkv(
    const float* __restrict__ x, const float* __restrict__ cp,
    const float* __restrict__ wq, const float* __restrict__ bq,
    const float* __restrict__ wkv, const float* __restrict__ bkv)
{
    const int b = blockIdx.z;
    const int nbase = blockIdx.x * 128;
    const int yb = blockIdx.y;

    const float* W;
    const float* X;
    const float* bias;
    float* OutB;
    if (yb < 2) {
        W = wq + yb * 128 * CC; X = x; bias = bq + yb * 128;
        OutB = g_Q + ((size_t)b * CC + yb * 128) * NN;
    } else {
        const int r = (yb - 2) * 128;
        W = wkv + r * CC; X = cp; bias = bkv + r;
        if (r < CC) OutB = g_K + ((size_t)b * CC + r) * NN;
        else        OutB = g_V + ((size_t)b * CC + (r - CC)) * NN;
    }

    float acc[4][4][4] = {};
    gemm_core_tf32<false>(W, CC, X + (size_t)b * CC * NN + nbase, NN, CC, acc);

    const int lane = threadIdx.x & 31, warp = threadIdx.x >> 5;
    const int wm = (warp >> 2) * 64, wn = (warp & 3) * 32;
    const int g = lane >> 2, tg = lane & 3;
#pragma unroll
    for (int i = 0; i < 4; i++) {
        const int r0 = wm + 16 * i + g;
        const float b0v = bias[r0], b1v = bias[r0 + 8];
#pragma unroll
        for (int j = 0; j < 4; j++) {
            const int col = nbase + wn + 8 * j + 2 * tg;
            *(float2*)&OutB[(size_t)r0 * NN + col] =
                make_float2(acc[i][j][0] + b0v, acc[i][j][1] + b0v);
            *(float2*)&OutB[(size_t)(r0 + 8) * NN + col] =
                make_float2(acc[i][j][2] + b1v, acc[i][j][3] + b1v);
        }
    }
}

// ---------------------------------------------------------------------------
// Kernel 2: softmax over N=4096 for each (b,c) row of K, in place.
// ---------------------------------------------------------------------------
__global__ __launch_bounds__(256) void softmax_k_kernel()
{
    float* p = g_K + (size_t)blockIdx.x * NN;
    const int t = threadIdx.x;
    __shared__ float sh[8];

    float v[16];
    float m = -1e30f;
#pragma unroll
    for (int i = 0; i < 16; i++) { v[i] = p[t + 256 * i]; m = fmaxf(m, v[i]); }
#pragma unroll
    for (int o = 16; o; o >>= 1) m = fmaxf(m, __shfl_xor_sync(0xffffffffu, m, o));
    if ((t & 31) == 0) sh[t >> 5] = m;
    __syncthreads();
    m = sh[0];
#pragma unroll
    for (int i = 1; i < 8; i++) m = fmaxf(m, sh[i]);

    float s = 0.f;
#pragma unroll
    for (int i = 0; i < 16; i++) { v[i] = __expf(v[i] - m); s += v[i]; }
#pragma unroll
    for (int o = 16; o; o >>= 1) s += __shfl_xor_sync(0xffffffffu, s, o);
    __syncthreads();
    if ((t & 31) == 0) sh[t >> 5] = s;
    __syncthreads();
    s = 0.f;
#pragma unroll
    for (int i = 0; i < 8; i++) s += sh[i];

    const float inv = 1.f / s;
#pragma unroll
    for (int i = 0; i < 16; i++) p[t + 256 * i] = v[i] * inv;
}

// ---------------------------------------------------------------------------
// Kernel 3: softmax over d=64 of 0.25*Q, in place. Values cached in regs.
// ---------------------------------------------------------------------------
__global__ __launch_bounds__(256) void softmax_q_kernel()
{
    const int idx = blockIdx.x * 256 + threadIdx.x;
    const int n = idx & (NN - 1);
    const int bh = idx >> 12;
    float* base = g_Q + (size_t)bh * 64 * NN + n;

    float v[64];
    float m = -1e30f;
#pragma unroll
    for (int d = 0; d < 64; d++) { v[d] = base[d * NN]; m = fmaxf(m, v[d]); }
    float s = 0.f;
#pragma unroll
    for (int d = 0; d < 64; d++) { v[d] = __expf((v[d] - m) * 0.25f); s += v[d]; }
    const float inv = 1.f / s;
#pragma unroll
    for (int d = 0; d < 64; d++) base[d * NN] = v[d] * inv;
}

// ---------------------------------------------------------------------------
// Kernel 4: context[b][c][d] = sum_n k[b][c][n] * V[b][d][n]   (A @ B^T)
// split-K in 8 chunks of 512; grid (2, 2, 64), 256 threads.
// ---------------------------------------------------------------------------
__global__ __launch_bounds__(256) void gemm_ctx()
{
    const int split = blockIdx.z & 7;
    const int b = blockIdx.z >> 3;
    const int mbase = blockIdx.y * 128;
    const int nbase = blockIdx.x * 128;
    const int k0 = split * 512;

    float acc[4][4][4] = {};
    gemm_core_tf32<true>(g_K + ((size_t)b * CC + mbase) * NN + k0, NN,
                         g_V + ((size_t)b * CC + nbase) * NN + k0, NN,
                         512, acc);

    float* Out = g_ctx[split] + ((size_t)b * CC + mbase) * CC + nbase;
    const int lane = threadIdx.x & 31, warp = threadIdx.x >> 5;
    const int wm = (warp >> 2) * 64, wn = (warp & 3) * 32;
    const int g = lane >> 2, tg = lane & 3;
#pragma unroll
    for (int i = 0; i < 4; i++) {
        const int r0 = wm + 16 * i + g;
#pragma unroll
        for (int j = 0; j < 4; j++) {
            const int col = wn + 8 * j + 2 * tg;
            *(float2*)&Out[(size_t)r0 * CC + col] = make_float2(acc[i][j][0], acc[i][j][1]);
            *(float2*)&Out[(size_t)(r0 + 8) * CC + col] = make_float2(acc[i][j][2], acc[i][j][3]);
        }
    }
}

// ---------------------------------------------------------------------------
// Kernel 5: Wc[b] = wo @ (sum of 8 ctx partials). SIMT fp32 (tiny GEMM).
// grid (4, 4, 8), 256 threads, 64x64 tiles.
// ---------------------------------------------------------------------------
__global__ __launch_bounds__(256) void gemm_wc(const float* __restrict__ wo)
{
    __shared__ __align__(16) float As[16][68];
    __shared__ __align__(16) float Bs[16][68];

    const int b = blockIdx.z;
    const int mbase = blockIdx.y * 64;
    const int nbase = blockIdx.x * 64;
    const float* Aptr = wo + mbase * CC;
    const size_t boff = (size_t)b * CC * CC + nbase;

    const int t = threadIdx.x;
    const int tx = t & 15, ty = t >> 4;
    const int arow = t >> 4, acol = t & 15;
    const int bcol = t & 63, brow = t >> 6;

    float acc[4][4] = {};
    for (int k0 = 0; k0 < CC; k0 += 16) {
#pragma unroll
        for (int r = 0; r < 4; r++)
            As[acol][arow + 16 * r] = Aptr[(arow + 16 * r) * CC + k0 + acol];
#pragma unroll
        for (int r = 0; r < 4; r++) {
            const size_t kr = boff + (size_t)(k0 + brow + 4 * r) * CC + bcol;
            float s = 0.f;
#pragma unroll
            for (int p = 0; p < NSPLIT; p++) s += g_ctx[p][kr];
            Bs[brow + 4 * r][bcol] = s;
        }
        __syncthreads();
#pragma unroll
        for (int kk = 0; kk < 16; kk++) {
            float4 a4 = *(const float4*)&As[kk][ty * 4];
            float4 b4 = *(const float4*)&Bs[kk][tx * 4];
            float av[4] = {a4.x, a4.y, a4.z, a4.w};
            float bw[4] = {b4.x, b4.y, b4.z, b4.w};
#pragma unroll
            for (int i = 0; i < 4; i++)
#pragma unroll
                for (int j = 0; j < 4; j++) acc[i][j] += av[i] * bw[j];
        }
        __syncthreads();
    }

    float* Out = g_Wc + ((size_t)b * CC + mbase) * CC + nbase;
#pragma unroll
    for (int i = 0; i < 4; i++)
        *(float4*)&Out[(ty * 4 + i) * CC + tx * 4] =
            make_float4(acc[i][0], acc[i][1], acc[i][2], acc[i][3]);
}

// ---------------------------------------------------------------------------
// Kernel 6: out[b] = Wc[b] @ q[b] + bo.  grid (32, 2, 8)
// ---------------------------------------------------------------------------
__global__ __launch_bounds__(256) void gemm_out(const float* __restrict__ bo,
                                                float* __restrict__ out)
{
    const int b = blockIdx.z;
    const int mbase = blockIdx.y * 128;
    const int nbase = blockIdx.x * 128;

    float acc[4][4][4] = {};
    gemm_core_tf32<false>(g_Wc + (size_t)b * CC * CC + mbase * CC, CC,
                          g_Q + (size_t)b * CC * NN + nbase, NN, CC, acc);

    float* OutB = out + ((size_t)b * CC + mbase) * NN + nbase;
    const int lane = threadIdx.x & 31, warp = threadIdx.x >> 5;
    const int wm = (warp >> 2) * 64, wn = (warp & 3) * 32;
    const int g = lane >> 2, tg = lane & 3;
#pragma unroll
    for (int i = 0; i < 4; i++) {
        const int r0 = wm + 16 * i + g;
        const float b0v = bo[mbase + r0], b1v = bo[mbase + r0 + 8];
#pragma unroll
        for (int j = 0; j < 4; j++) {
            const int col = wn + 8 * j + 2 * tg;
            *(float2*)&OutB[(size_t)r0 * NN + col] =
                make_float2(acc[i][j][0] + b0v, acc[i][j][1] + b0v);
            *(float2*)&OutB[(size_t)(r0 + 8) * NN + col] =
                make_float2(acc[i][j][2] + b1v, acc[i][j][3] + b1v);
        }
    }
}

// ---------------------------------------------------------------------------
extern "C" void kernel_launch(void* const* d_in, const int* in_sizes, int n_in,
                              void* d_out, int out_size)
{
    const float* x    = (const float*)d_in[0];
    const float* cp   = (const float*)d_in[1];
    const float* wq   = (const float*)d_in[2];
    const float* bq   = (const float*)d_in[3];
    const float* wkv  = (const float*)d_in[4];
    const float* bkv  = (const float*)d_in[5];
    const float* wo   = (const float*)d_in[6];
    const float* bo   = (const float*)d_in[7];
    float* out = (float*)d_out;

    gemm_qkv<<<dim3(32, 6, 8), 256>>>(x, cp, wq, bq, wkv, bkv);
    softmax_k_kernel<<<2048, 256>>>();
    softmax_q_kernel<<<512, 256>>>();
    gemm_ctx<<<dim3(2, 2, 64), 256>>>();
    gemm_wc<<<dim3(4, 4, 8), 256>>>(wo);
    gemm_out<<<dim3(32, 2, 8), 256>>>(bo, out);
}

// round 4
// speedup vs baseline: 3.0113x; 1.8097x over previous
#include <cuda_runtime.h>
#include <cuda_fp16.h>
#include <cstdint>

#define BB 8
#define CC 256
#define NN 4096
#define NSPLIT 8

// Scratch (device globals — no allocation allowed)
__device__ __align__(128) float g_Q[BB * CC * NN];          // 32 MB
__device__ __align__(128) float g_K[BB * CC * NN];          // 32 MB (holds k * 4096 after softmax)
__device__ __align__(128) float g_V[BB * CC * NN];          // 32 MB
__device__ __align__(128) float g_ctx[NSPLIT][BB * CC * CC];// 16 MB split-K partials (x4096)
__device__ __align__(128) float g_Wc[BB * CC * CC];         // 2 MB

// ---------------------------------------------------------------------------
// helpers
// ---------------------------------------------------------------------------
__device__ __forceinline__ uint32_t smem_u32(const void* p) {
    uint32_t a;
    asm("{ .reg .u64 t; cvta.to.shared.u64 t, %1; cvt.u32.u64 %0, t; }" : "=r"(a) : "l"(p));
    return a;
}

__device__ __forceinline__ void ldmx4(uint32_t* r, uint32_t addr) {
    asm volatile("ldmatrix.sync.aligned.m8n8.x4.shared.b16 {%0,%1,%2,%3}, [%4];"
                 : "=r"(r[0]), "=r"(r[1]), "=r"(r[2]), "=r"(r[3]) : "r"(addr));
}
__device__ __forceinline__ void ldmx4t(uint32_t* r, uint32_t addr) {
    asm volatile("ldmatrix.sync.aligned.m8n8.x4.trans.shared.b16 {%0,%1,%2,%3}, [%4];"
                 : "=r"(r[0]), "=r"(r[1]), "=r"(r[2]), "=r"(r[3]) : "r"(addr));
}
__device__ __forceinline__ void mma16816(float* c, const uint32_t* a, const uint32_t* b) {
    asm volatile(
        "mma.sync.aligned.m16n8k16.row.col.f32.f16.f16.f32 "
        "{%0,%1,%2,%3}, {%4,%5,%6,%7}, {%8,%9}, {%0,%1,%2,%3};"
        : "+f"(c[0]), "+f"(c[1]), "+f"(c[2]), "+f"(c[3])
        : "r"(a[0]), "r"(a[1]), "r"(a[2]), "r"(a[3]), "r"(b[0]), "r"(b[1]));
}

__device__ __forceinline__ uint4 pack8(float4 a, float4 b) {
    uint4 u;
    half2 h;
    h = __floats2half2_rn(a.x, a.y); u.x = *(const uint32_t*)&h;
    h = __floats2half2_rn(a.z, a.w); u.y = *(const uint32_t*)&h;
    h = __floats2half2_rn(b.x, b.y); u.z = *(const uint32_t*)&h;
    h = __floats2half2_rn(b.z, b.w); u.w = *(const uint32_t*)&h;
    return u;
}

// ---------------------------------------------------------------------------
// fp16 tensor-core GEMM core: C[128x128] += A[128xK] * B
// BKN=false: B stored [n][ldb] K-major (C = A * B^T)
// BKN=true : B stored [k][ldb] rows, n contiguous
// 256 threads, 8 warps (2x4), warp tile 64x32, m16n8k16, BK=32.
// ---------------------------------------------------------------------------
template <bool BKN>
struct Sm {
    __align__(16) half A[2][128][40];
    __align__(16) half B[2][BKN ? 32 : 128][BKN ? 136 : 40];
};

struct Stage { uint4 a0, a1, b0, b1; };

template <bool BKN>
__device__ __forceinline__ void loadg(Stage& st, const float* __restrict__ A, int lda,
                                      const float* __restrict__ B, int ldb, int t) {
    {
        const int row = t >> 1, seg = t & 1;
        const float* p = A + (size_t)row * lda + seg * 16;
        float4 f0 = *(const float4*)p, f1 = *(const float4*)(p + 4);
        float4 f2 = *(const float4*)(p + 8), f3 = *(const float4*)(p + 12);
        st.a0 = pack8(f0, f1);
        st.a1 = pack8(f2, f3);
    }
    if (BKN) {
        const int row = t >> 3, g = t & 7;
        const float* p = B + (size_t)row * ldb + g * 16;
        float4 f0 = *(const float4*)p, f1 = *(const float4*)(p + 4);
        float4 f2 = *(const float4*)(p + 8), f3 = *(const float4*)(p + 12);
        st.b0 = pack8(f0, f1);
        st.b1 = pack8(f2, f3);
    } else {
        const int row = t >> 1, seg = t & 1;
        const float* p = B + (size_t)row * ldb + seg * 16;
        float4 f0 = *(const float4*)p, f1 = *(const float4*)(p + 4);
        float4 f2 = *(const float4*)(p + 8), f3 = *(const float4*)(p + 12);
        st.b0 = pack8(f0, f1);
        st.b1 = pack8(f2, f3);
    }
}

template <bool BKN>
__device__ __forceinline__ void stosm(Sm<BKN>* s, int buf, const Stage& st, int t) {
    {
        const int row = t >> 1, seg = t & 1;
        *(uint4*)&s->A[buf][row][seg * 16] = st.a0;
        *(uint4*)&s->A[buf][row][seg * 16 + 8] = st.a1;
    }
    if (BKN) {
        const int row = t >> 3, g = t & 7;
        *(uint4*)&s->B[buf][row][g * 16] = st.b0;
        *(uint4*)&s->B[buf][row][g * 16 + 8] = st.b1;
    } else {
        const int row = t >> 1, seg = t & 1;
        *(uint4*)&s->B[buf][row][seg * 16] = st.b0;
        *(uint4*)&s->B[buf][row][seg * 16 + 8] = st.b1;
    }
}

template <bool BKN>
__device__ __forceinline__ void compute(Sm<BKN>* s, int buf, float acc[4][4][4],
                                        int wm, int wn, int lane) {
#pragma unroll
    for (int ks = 0; ks < 32; ks += 16) {
        uint32_t af[4][4];
#pragma unroll
        for (int mi = 0; mi < 4; mi++)
            ldmx4(af[mi],
                  smem_u32(&s->A[buf][wm + 16 * mi + (lane & 15)][ks + ((lane >> 4) << 3)]));
        uint32_t bf[4][2];
#pragma unroll
        for (int nj2 = 0; nj2 < 2; nj2++) {
            uint32_t r[4];
            if (BKN)
                ldmx4t(r, smem_u32(&s->B[buf][ks + (((lane >> 3) & 1) << 3) + (lane & 7)]
                                          [wn + nj2 * 16 + ((lane >> 4) << 3)]));
            else
                ldmx4(r, smem_u32(&s->B[buf][wn + nj2 * 16 + ((lane >> 4) << 3) + (lane & 7)]
                                         [ks + (((lane >> 3) & 1) << 3)]));
            bf[2 * nj2][0] = r[0]; bf[2 * nj2][1] = r[1];
            bf[2 * nj2 + 1][0] = r[2]; bf[2 * nj2 + 1][1] = r[3];
        }
#pragma unroll
        for (int mi = 0; mi < 4; mi++)
#pragma unroll
            for (int nj = 0; nj < 4; nj++)
                mma16816(acc[mi][nj], af[mi], bf[nj]);
    }
}

template <bool BKN>
__device__ __forceinline__ void gemm_run(Sm<BKN>* s, const float* __restrict__ A, int lda,
                                         const float* __restrict__ B, int ldb,
                                         int nIter, float acc[4][4][4]) {
    const int t = threadIdx.x, lane = t & 31, warp = t >> 5;
    const int wm = (warp >> 2) * 64, wn = (warp & 3) * 32;

    Stage st;
    loadg<BKN>(st, A, lda, B, ldb, t);
    stosm<BKN>(s, 0, st, t);
    __syncthreads();
    for (int it = 0; it < nIter; ++it) {
        const int cur = it & 1;
        if (it + 1 < nIter) {
            const float* An = A + (it + 1) * 32;
            const float* Bn = BKN ? B + (size_t)(it + 1) * 32 * ldb : B + (it + 1) * 32;
            loadg<BKN>(st, An, lda, Bn, ldb, t);
        }
        compute<BKN>(s, cur, acc, wm, wn, lane);
        if (it + 1 < nIter) stosm<BKN>(s, cur ^ 1, st, t);
        __syncthreads();
    }
}

// ---------------------------------------------------------------------------
// Kernel 1: Q = wq@x + bq (y=0..1), KV = wkv@cproj + bkv (y=2..5)
// grid (32, 6, 8), 256 threads
// ---------------------------------------------------------------------------
__global__ __launch_bounds__(256) void gemm_qkv(
    const float* __restrict__ x, const float* __restrict__ cp,
    const float* __restrict__ wq, const float* __restrict__ bq,
    const float* __restrict__ wkv, const float* __restrict__ bkv)
{
    __shared__ Sm<true> s;
    const int b = blockIdx.z;
    const int nbase = blockIdx.x * 128;
    const int yb = blockIdx.y;

    const float* W;
    const float* X;
    const float* bias;
    float* OutB;
    if (yb < 2) {
        W = wq + yb * 128 * CC; X = x; bias = bq + yb * 128;
        OutB = g_Q + ((size_t)b * CC + yb * 128) * NN;
    } else {
        const int r = (yb - 2) * 128;
        W = wkv + r * CC; X = cp; bias = bkv + r;
        if (r < CC) OutB = g_K + ((size_t)b * CC + r) * NN;
        else        OutB = g_V + ((size_t)b * CC + (r - CC)) * NN;
    }

    float acc[4][4][4] = {};
    gemm_run<true>(&s, W, CC, X + (size_t)b * CC * NN + nbase, NN, CC / 32, acc);

    const int lane = threadIdx.x & 31, warp = threadIdx.x >> 5;
    const int wm = (warp >> 2) * 64, wn = (warp & 3) * 32;
    const int g = lane >> 2, tg = lane & 3;
#pragma unroll
    for (int i = 0; i < 4; i++) {
        const int r0 = wm + 16 * i + g;
        const float b0v = bias[r0], b1v = bias[r0 + 8];
#pragma unroll
        for (int j = 0; j < 4; j++) {
            const int col = nbase + wn + 8 * j + 2 * tg;
            *(float2*)&OutB[(size_t)r0 * NN + col] =
                make_float2(acc[i][j][0] + b0v, acc[i][j][1] + b0v);
            *(float2*)&OutB[(size_t)(r0 + 8) * NN + col] =
                make_float2(acc[i][j][2] + b1v, acc[i][j][3] + b1v);
        }
    }
}

// ---------------------------------------------------------------------------
// Kernel 2: softmax over N=4096 for each (b,c) row of K; output scaled x4096.
// ---------------------------------------------------------------------------
__global__ __launch_bounds__(256) void softmax_k_kernel()
{
    float* p = g_K + (size_t)blockIdx.x * NN;
    const int t = threadIdx.x;
    __shared__ float sh[8];

    float v[16];
    float m = -1e30f;
#pragma unroll
    for (int i = 0; i < 16; i++) { v[i] = p[t + 256 * i]; m = fmaxf(m, v[i]); }
#pragma unroll
    for (int o = 16; o; o >>= 1) m = fmaxf(m, __shfl_xor_sync(0xffffffffu, m, o));
    if ((t & 31) == 0) sh[t >> 5] = m;
    __syncthreads();
    m = sh[0];
#pragma unroll
    for (int i = 1; i < 8; i++) m = fmaxf(m, sh[i]);

    float s = 0.f;
#pragma unroll
    for (int i = 0; i < 16; i++) { v[i] = __expf(v[i] - m); s += v[i]; }
#pragma unroll
    for (int o = 16; o; o >>= 1) s += __shfl_xor_sync(0xffffffffu, s, o);
    __syncthreads();
    if ((t & 31) == 0) sh[t >> 5] = s;
    __syncthreads();
    s = 0.f;
#pragma unroll
    for (int i = 0; i < 8; i++) s += sh[i];

    const float inv = 4096.f / s;   // scaled for fp16 range
#pragma unroll
    for (int i = 0; i < 16; i++) p[t + 256 * i] = v[i] * inv;
}

// ---------------------------------------------------------------------------
// Kernel 3: softmax over d=64 of 0.25*Q, in place; output scaled x64.
// ---------------------------------------------------------------------------
__global__ __launch_bounds__(256) void softmax_q_kernel()
{
    const int idx = blockIdx.x * 256 + threadIdx.x;
    const int n = idx & (NN - 1);
    const int bh = idx >> 12;
    float* base = g_Q + (size_t)bh * 64 * NN + n;

    float v[64];
    float m = -1e30f;
#pragma unroll
    for (int d = 0; d < 64; d++) { v[d] = base[d * NN]; m = fmaxf(m, v[d]); }
    float s = 0.f;
#pragma unroll
    for (int d = 0; d < 64; d++) { v[d] = __expf((v[d] - m) * 0.25f); s += v[d]; }
    const float inv = 64.f / s;     // scaled for fp16 range
#pragma unroll
    for (int d = 0; d < 64; d++) base[d * NN] = v[d] * inv;
}

// ---------------------------------------------------------------------------
// Kernel 4: ctx partial (x4096) = k_s-tile @ V-tile^T over split n-range.
// grid (2, 2, 64): z = b*8 + split, K=512 per split.
// ---------------------------------------------------------------------------
__global__ __launch_bounds__(256) void gemm_ctx()
{
    __shared__ Sm<false> s;
    const int split = blockIdx.z & 7;
    const int b = blockIdx.z >> 3;
    const int mbase = blockIdx.y * 128;
    const int nbase = blockIdx.x * 128;
    const int k0 = split * 512;

    float acc[4][4][4] = {};
    gemm_run<false>(&s, g_K + ((size_t)b * CC + mbase) * NN + k0, NN,
                    g_V + ((size_t)b * CC + nbase) * NN + k0, NN, 512 / 32, acc);

    float* Out = g_ctx[split] + ((size_t)b * CC + mbase) * CC + nbase;
    const int lane = threadIdx.x & 31, warp = threadIdx.x >> 5;
    const int wm = (warp >> 2) * 64, wn = (warp & 3) * 32;
    const int g = lane >> 2, tg = lane & 3;
#pragma unroll
    for (int i = 0; i < 4; i++) {
        const int r0 = wm + 16 * i + g;
#pragma unroll
        for (int j = 0; j < 4; j++) {
            const int col = wn + 8 * j + 2 * tg;
            *(float2*)&Out[(size_t)r0 * CC + col] = make_float2(acc[i][j][0], acc[i][j][1]);
            *(float2*)&Out[(size_t)(r0 + 8) * CC + col] = make_float2(acc[i][j][2], acc[i][j][3]);
        }
    }
}

// ---------------------------------------------------------------------------
// Kernel 5: Wc[b] = wo @ (sum of 8 ctx partials) / 4096. SIMT fp32 (tiny).
// grid (4, 4, 8), 256 threads, 64x64 tiles.
// ---------------------------------------------------------------------------
__global__ __launch_bounds__(256) void gemm_wc(const float* __restrict__ wo)
{
    __shared__ __align__(16) float As[16][68];
    __shared__ __align__(16) float Bs[16][68];

    const int b = blockIdx.z;
    const int mbase = blockIdx.y * 64;
    const int nbase = blockIdx.x * 64;
    const float* Aptr = wo + mbase * CC;
    const size_t boff = (size_t)b * CC * CC + nbase;

    const int t = threadIdx.x;
    const int tx = t & 15, ty = t >> 4;
    const int arow = t >> 4, acol = t & 15;
    const int bcol = t & 63, brow = t >> 6;

    float acc[4][4] = {};
    for (int k0 = 0; k0 < CC; k0 += 16) {
#pragma unroll
        for (int r = 0; r < 4; r++)
            As[acol][arow + 16 * r] = Aptr[(arow + 16 * r) * CC + k0 + acol];
#pragma unroll
        for (int r = 0; r < 4; r++) {
            const size_t kr = boff + (size_t)(k0 + brow + 4 * r) * CC + bcol;
            float s = 0.f;
#pragma unroll
            for (int p = 0; p < NSPLIT; p++) s += g_ctx[p][kr];
            Bs[brow + 4 * r][bcol] = s * (1.f / 4096.f);   // undo k scale
        }
        __syncthreads();
#pragma unroll
        for (int kk = 0; kk < 16; kk++) {
            float4 a4 = *(const float4*)&As[kk][ty * 4];
            float4 b4 = *(const float4*)&Bs[kk][tx * 4];
            float av[4] = {a4.x, a4.y, a4.z, a4.w};
            float bw[4] = {b4.x, b4.y, b4.z, b4.w};
#pragma unroll
            for (int i = 0; i < 4; i++)
#pragma unroll
                for (int j = 0; j < 4; j++) acc[i][j] += av[i] * bw[j];
        }
        __syncthreads();
    }

    float* Out = g_Wc + ((size_t)b * CC + mbase) * CC + nbase;
#pragma unroll
    for (int i = 0; i < 4; i++)
        *(float4*)&Out[(ty * 4 + i) * CC + tx * 4] =
            make_float4(acc[i][0], acc[i][1], acc[i][2], acc[i][3]);
}

// ---------------------------------------------------------------------------
// Kernel 6: out[b] = Wc[b] @ q_s[b] / 64 + bo.  grid (32, 2, 8)
// ---------------------------------------------------------------------------
__global__ __launch_bounds__(256) void gemm_out(const float* __restrict__ bo,
                                                float* __restrict__ out)
{
    __shared__ Sm<true> s;
    const int b = blockIdx.z;
    const int mbase = blockIdx.y * 128;
    const int nbase = blockIdx.x * 128;

    float acc[4][4][4] = {};
    gemm_run<true>(&s, g_Wc + (size_t)b * CC * CC + mbase * CC, CC,
                   g_Q + (size_t)b * CC * NN + nbase, NN, CC / 32, acc);

    constexpr float IS = 1.f / 64.f;   // undo q scale
    float* OutB = out + ((size_t)b * CC + mbase) * NN + nbase;
    const int lane = threadIdx.x & 31, warp = threadIdx.x >> 5;
    const int wm = (warp >> 2) * 64, wn = (warp & 3) * 32;
    const int g = lane >> 2, tg = lane & 3;
#pragma unroll
    for (int i = 0; i < 4; i++) {
        const int r0 = wm + 16 * i + g;
        const float b0v = bo[mbase + r0], b1v = bo[mbase + r0 + 8];
#pragma unroll
        for (int j = 0; j < 4; j++) {
            const int col = wn + 8 * j + 2 * tg;
            *(float2*)&OutB[(size_t)r0 * NN + col] =
                make_float2(acc[i][j][0] * IS + b0v, acc[i][j][1] * IS + b0v);
            *(float2*)&OutB[(size_t)(r0 + 8) * NN + col] =
                make_float2(acc[i][j][2] * IS + b1v, acc[i][j][3] * IS + b1v);
        }
    }
}

// ---------------------------------------------------------------------------
extern "C" void kernel_launch(void* const* d_in, const int* in_sizes, int n_in,
                              void* d_out, int out_size)
{
    const float* x    = (const float*)d_in[0];
    const float* cp   = (const float*)d_in[1];
    const float* wq   = (const float*)d_in[2];
    const float* bq   = (const float*)d_in[3];
    const float* wkv  = (const float*)d_in[4];
    const float* bkv  = (const float*)d_in[5];
    const float* wo   = (const float*)d_in[6];
    const float* bo   = (const float*)d_in[7];
    float* out = (float*)d_out;

    gemm_qkv<<<dim3(32, 6, 8), 256>>>(x, cp, wq, bq, wkv, bkv);
    softmax_k_kernel<<<2048, 256>>>();
    softmax_q_kernel<<<512, 256>>>();
    gemm_ctx<<<dim3(2, 2, 64), 256>>>();
    gemm_wc<<<dim3(4, 4, 8), 256>>>(wo);
    gemm_out<<<dim3(32, 2, 8), 256>>>(bo, out);
}

// round 6
// speedup vs baseline: 3.9406x; 1.3086x over previous
#include <cuda_runtime.h>
#include <cuda_fp16.h>
#include <cstdint>

#define BB 8
#define CC 256
#define NN 4096
#define NSPLIT 8

// Scratch (device globals — no allocation allowed)
__device__ __align__(128) half  g_Xh[BB * CC * NN];          // 16 MB  x in fp16
__device__ __align__(128) half  g_Ch[BB * CC * NN];          // 16 MB  cproj in fp16
__device__ __align__(128) half  g_Wqh[CC * CC];              // wq fp16
__device__ __align__(128) half  g_Wkvh[2 * CC * CC];         // wkv fp16
__device__ __align__(128) float g_Q[BB * CC * NN];           // 32 MB  Q logits fp32
__device__ __align__(128) float g_K[BB * CC * NN];           // 32 MB  K logits fp32
__device__ __align__(128) half  g_Vh[BB * CC * NN];          // 16 MB  V fp16
__device__ __align__(128) half  g_Kh[BB * CC * NN];          // 16 MB  softmax(K)*4096 fp16
__device__ __align__(128) half  g_Qh[BB * CC * NN];          // 16 MB  softmax(Q)*64 fp16
__device__ __align__(128) float g_ctx[NSPLIT][BB * CC * CC]; // 16 MB  split-K partials
__device__ __align__(128) half  g_Wch[BB * CC * CC];         // 1 MB   wo@ctx fp16

// ---------------------------------------------------------------------------
// helpers
// ---------------------------------------------------------------------------
__device__ __forceinline__ uint32_t smem_u32(const void* p) {
    uint32_t a;
    asm("{ .reg .u64 t; cvta.to.shared.u64 t, %1; cvt.u32.u64 %0, t; }" : "=r"(a) : "l"(p));
    return a;
}
__device__ __forceinline__ void cpa16(uint32_t dst, const void* src) {
    asm volatile("cp.async.cg.shared.global [%0], [%1], 16;" :: "r"(dst), "l"(src));
}
__device__ __forceinline__ void ldmx4(uint32_t* r, uint32_t addr) {
    asm volatile("ldmatrix.sync.aligned.m8n8.x4.shared.b16 {%0,%1,%2,%3}, [%4];"
                 : "=r"(r[0]), "=r"(r[1]), "=r"(r[2]), "=r"(r[3]) : "r"(addr));
}
__device__ __forceinline__ void ldmx4t(uint32_t* r, uint32_t addr) {
    asm volatile("ldmatrix.sync.aligned.m8n8.x4.trans.shared.b16 {%0,%1,%2,%3}, [%4];"
                 : "=r"(r[0]), "=r"(r[1]), "=r"(r[2]), "=r"(r[3]) : "r"(addr));
}
__device__ __forceinline__ void mma16816(float* c, const uint32_t* a, const uint32_t* b) {
    asm volatile(
        "mma.sync.aligned.m16n8k16.row.col.f32.f16.f16.f32 "
        "{%0,%1,%2,%3}, {%4,%5,%6,%7}, {%8,%9}, {%0,%1,%2,%3};"
        : "+f"(c[0]), "+f"(c[1]), "+f"(c[2]), "+f"(c[3])
        : "r"(a[0]), "r"(a[1]), "r"(a[2]), "r"(a[3]), "r"(b[0]), "r"(b[1]));
}
__device__ __forceinline__ uint4 pack8(float4 a, float4 b) {
    uint4 u;
    half2 h;
    h = __floats2half2_rn(a.x, a.y); u.x = *(const uint32_t*)&h;
    h = __floats2half2_rn(a.z, a.w); u.y = *(const uint32_t*)&h;
    h = __floats2half2_rn(b.x, b.y); u.z = *(const uint32_t*)&h;
    h = __floats2half2_rn(b.z, b.w); u.w = *(const uint32_t*)&h;
    return u;
}

// ---------------------------------------------------------------------------
// fp16 cp.async 3-stage GEMM core: C[128x128] += A[128xK] * B
// BKN=false: B [n][ldb] K-major (C = A * B^T);  BKN=true: B [k][ldb], n contig
// 256 threads, 8 warps (2x4), warp tile 64x32, m16n8k16, BK=32, NST=3.
// ---------------------------------------------------------------------------
template <bool BKN>
struct SmP {
    __align__(16) half A[3][128][40];
    __align__(16) half B[3][BKN ? 32 : 128][BKN ? 136 : 40];
};

template <bool BKN>
__device__ __forceinline__ void issue_stage(SmP<BKN>* s, int st,
                                            const half* __restrict__ Asrc, int lda,
                                            const half* __restrict__ Bsrc, int ldb, int t) {
#pragma unroll
    for (int r = 0; r < 2; r++) {
        const int idx = t + 256 * r;
        const int row = idx >> 2, seg = idx & 3;
        cpa16(smem_u32(&s->A[st][row][seg * 8]), Asrc + (size_t)row * lda + seg * 8);
    }
    if (BKN) {
#pragma unroll
        for (int r = 0; r < 2; r++) {
            const int idx = t + 256 * r;
            const int row = idx >> 4, seg = idx & 15;
            cpa16(smem_u32(&s->B[st][row][seg * 8]), Bsrc + (size_t)row * ldb + seg * 8);
        }
    } else {
#pragma unroll
        for (int r = 0; r < 2; r++) {
            const int idx = t + 256 * r;
            const int row = idx >> 2, seg = idx & 3;
            cpa16(smem_u32(&s->B[st][row][seg * 8]), Bsrc + (size_t)row * ldb + seg * 8);
        }
    }
}

template <bool BKN>
__device__ __forceinline__ void compute(SmP<BKN>* s, int buf, float acc[4][4][4],
                                        int wm, int wn, int lane) {
#pragma unroll
    for (int ks = 0; ks < 32; ks += 16) {
        uint32_t af[4][4];
#pragma unroll
        for (int mi = 0; mi < 4; mi++)
            ldmx4(af[mi],
                  smem_u32(&s->A[buf][wm + 16 * mi + (lane & 15)][ks + ((lane >> 4) << 3)]));
        uint32_t bf[4][2];
#pragma unroll
        for (int nj2 = 0; nj2 < 2; nj2++) {
            uint32_t r[4];
            if (BKN)
                ldmx4t(r, smem_u32(&s->B[buf][ks + (((lane >> 3) & 1) << 3) + (lane & 7)]
                                          [wn + nj2 * 16 + ((lane >> 4) << 3)]));
            else
                ldmx4(r, smem_u32(&s->B[buf][wn + nj2 * 16 + ((lane >> 4) << 3) + (lane & 7)]
                                         [ks + (((lane >> 3) & 1) << 3)]));
            bf[2 * nj2][0] = r[0]; bf[2 * nj2][1] = r[1];
            bf[2 * nj2 + 1][0] = r[2]; bf[2 * nj2 + 1][1] = r[3];
        }
#pragma unroll
        for (int mi = 0; mi < 4; mi++)
#pragma unroll
            for (int nj = 0; nj < 4; nj++)
                mma16816(acc[mi][nj], af[mi], bf[nj]);
    }
}

template <bool BKN>
__device__ __forceinline__ void gemm_run(SmP<BKN>* s, const half* __restrict__ A, int lda,
                                         const half* __restrict__ B, int ldb,
                                         int nIter, float acc[4][4][4]) {
    const int t = threadIdx.x, lane = t & 31, warp = t >> 5;
    const int wm = (warp >> 2) * 64, wn = (warp & 3) * 32;

#pragma unroll
    for (int st = 0; st < 2; st++) {
        if (st < nIter)
            issue_stage<BKN>(s, st, A + st * 32, lda,
                             BKN ? B + (size_t)st * 32 * ldb : B + st * 32, ldb, t);
        asm volatile("cp.async.commit_group;" ::: "memory");
    }
    int cur = 0;
    for (int it = 0; it < nIter; ++it) {
        asm volatile("cp.async.wait_group 1;" ::: "memory");
        __syncthreads();
        compute<BKN>(s, cur, acc, wm, wn, lane);
        const int nxt = it + 2;
        if (nxt < nIter) {
            int nst = cur + 2; if (nst >= 3) nst -= 3;
            issue_stage<BKN>(s, nst, A + nxt * 32, lda,
                             BKN ? B + (size_t)nxt * 32 * ldb : B + nxt * 32, ldb, t);
        }
        asm volatile("cp.async.commit_group;" ::: "memory");
        if (++cur == 3) cur = 0;
    }
}

// ---------------------------------------------------------------------------
// Kernel 0a: convert x / cproj -> fp16.  grid (4096, 2), 256 thr, 8 elems/thr
// ---------------------------------------------------------------------------
__global__ __launch_bounds__(256) void conv_inputs(const float* __restrict__ x,
                                                   const float* __restrict__ cp)
{
    const int gid = blockIdx.x * 256 + threadIdx.x;
    const float* src = blockIdx.y ? cp : x;
    half* dst = blockIdx.y ? g_Ch : g_Xh;
    const size_t o = (size_t)gid * 8;
    float4 a = *(const float4*)(src + o);
    float4 b = *(const float4*)(src + o + 4);
    *(uint4*)(dst + o) = pack8(a, b);
}

// Kernel 0b: convert wq, wkv -> fp16.  grid 96, 256 thr, 8 elems/thr
__global__ __launch_bounds__(256) void conv_w(const float* __restrict__ wq,
                                              const float* __restrict__ wkv)
{
    const size_t o = (size_t)(blockIdx.x * 256 + threadIdx.x) * 8;
    const float* src;
    half* dst;
    size_t oo;
    if (o < CC * CC) { src = wq;  dst = g_Wqh;  oo = o; }
    else             { src = wkv; dst = g_Wkvh; oo = o - CC * CC; }
    float4 a = *(const float4*)(src + oo);
    float4 b = *(const float4*)(src + oo + 4);
    *(uint4*)(dst + oo) = pack8(a, b);
}

// ---------------------------------------------------------------------------
// Kernel 1: Q = wq@x + bq (y=0..1), KV = wkv@cproj + bkv (y=2..5)
// grid (32, 6, 8), 256 threads, dynamic smem
// ---------------------------------------------------------------------------
__global__ __launch_bounds__(256) void gemm_qkv(
    const float* __restrict__ bq, const float* __restrict__ bkv)
{
    extern __shared__ __align__(16) char dyn[];
    SmP<true>* s = reinterpret_cast<SmP<true>*>(dyn);

    const int b = blockIdx.z;
    const int nbase = blockIdx.x * 128;
    const int yb = blockIdx.y;

    const half* W;
    const half* X;
    const float* bias;
    int kind;   // 0=Q fp32, 1=K fp32, 2=V half
    float* OutF = nullptr;
    half* OutH = nullptr;
    if (yb < 2) {
        W = g_Wqh + yb * 128 * CC; X = g_Xh; bias = bq + yb * 128; kind = 0;
        OutF = g_Q + ((size_t)b * CC + yb * 128) * NN;
    } else {
        const int r = (yb - 2) * 128;
        W = g_Wkvh + r * CC; X = g_Ch; bias = bkv + r;
        if (r < CC) { kind = 1; OutF = g_K + ((size_t)b * CC + r) * NN; }
        else        { kind = 2; OutH = g_Vh + ((size_t)b * CC + (r - CC)) * NN; }
    }

    float acc[4][4][4] = {};
    gemm_run<true>(s, W, CC, X + (size_t)b * CC * NN + nbase, NN, CC / 32, acc);

    const int lane = threadIdx.x & 31, warp = threadIdx.x >> 5;
    const int wm = (warp >> 2) * 64, wn = (warp & 3) * 32;
    const int g = lane >> 2, tg = lane & 3;
#pragma unroll
    for (int i = 0; i < 4; i++) {
        const int r0 = wm + 16 * i + g;
        const float b0v = bias[r0], b1v = bias[r0 + 8];
#pragma unroll
        for (int j = 0; j < 4; j++) {
            const int col = nbase + wn + 8 * j + 2 * tg;
            if (kind < 2) {
                *(float2*)&OutF[(size_t)r0 * NN + col] =
                    make_float2(acc[i][j][0] + b0v, acc[i][j][1] + b0v);
                *(float2*)&OutF[(size_t)(r0 + 8) * NN + col] =
                    make_float2(acc[i][j][2] + b1v, acc[i][j][3] + b1v);
            } else {
                *(__half2*)&OutH[(size_t)r0 * NN + col] =
                    __floats2half2_rn(acc[i][j][0] + b0v, acc[i][j][1] + b0v);
                *(__half2*)&OutH[(size_t)(r0 + 8) * NN + col] =
                    __floats2half2_rn(acc[i][j][2] + b1v, acc[i][j][3] + b1v);
            }
        }
    }
}

// ---------------------------------------------------------------------------
// Kernel 2: softmax over N=4096 rows of K (fp32) -> g_Kh (fp16, x4096)
// ---------------------------------------------------------------------------
__global__ __launch_bounds__(256) void softmax_k_kernel()
{
    const float* p = g_K + (size_t)blockIdx.x * NN;
    half* po = g_Kh + (size_t)blockIdx.x * NN;
    const int t = threadIdx.x;
    __shared__ float sh[8];

    float v[16];
    float m = -1e30f;
#pragma unroll
    for (int i = 0; i < 16; i++) { v[i] = p[t + 256 * i]; m = fmaxf(m, v[i]); }
#pragma unroll
    for (int o = 16; o; o >>= 1) m = fmaxf(m, __shfl_xor_sync(0xffffffffu, m, o));
    if ((t & 31) == 0) sh[t >> 5] = m;
    __syncthreads();
    m = sh[0];
#pragma unroll
    for (int i = 1; i < 8; i++) m = fmaxf(m, sh[i]);

    float s = 0.f;
#pragma unroll
    for (int i = 0; i < 16; i++) { v[i] = __expf(v[i] - m); s += v[i]; }
#pragma unroll
    for (int o = 16; o; o >>= 1) s += __shfl_xor_sync(0xffffffffu, s, o);
    __syncthreads();
    if ((t & 31) == 0) sh[t >> 5] = s;
    __syncthreads();
    s = 0.f;
#pragma unroll
    for (int i = 0; i < 8; i++) s += sh[i];

    const float inv = 4096.f / s;
#pragma unroll
    for (int i = 0; i < 16; i++) po[t + 256 * i] = __float2half(v[i] * inv);
}

// ---------------------------------------------------------------------------
// Kernel 3: softmax over d=64 of 0.25*Q (fp32) -> g_Qh (fp16, x64)
// ---------------------------------------------------------------------------
__global__ __launch_bounds__(256) void softmax_q_kernel()
{
    const int idx = blockIdx.x * 256 + threadIdx.x;
    const int n = idx & (NN - 1);
    const int bh = idx >> 12;
    const float* base = g_Q + (size_t)bh * 64 * NN + n;
    half* baseo = g_Qh + (size_t)bh * 64 * NN + n;

    float v[64];
    float m = -1e30f;
#pragma unroll
    for (int d = 0; d < 64; d++) { v[d] = base[d * NN]; m = fmaxf(m, v[d]); }
    float s = 0.f;
#pragma unroll
    for (int d = 0; d < 64; d++) { v[d] = __expf((v[d] - m) * 0.25f); s += v[d]; }
    const float inv = 64.f / s;
#pragma unroll
    for (int d = 0; d < 64; d++) baseo[d * NN] = __float2half(v[d] * inv);
}

// ---------------------------------------------------------------------------
// Kernel 4: ctx partial (x4096) = k_s-tile @ V-tile^T over split n-range.
// grid (2, 2, 64): z = b*8 + split, K=512 per split.  dynamic smem
// ---------------------------------------------------------------------------
__global__ __launch_bounds__(256) void gemm_ctx()
{
    extern __shared__ __align__(16) char dyn[];
    SmP<false>* s = reinterpret_cast<SmP<false>*>(dyn);

    const int split = blockIdx.z & 7;
    const int b = blockIdx.z >> 3;
    const int mbase = blockIdx.y * 128;
    const int nbase = blockIdx.x * 128;
    const int k0 = split * 512;

    float acc[4][4][4] = {};
    gemm_run<false>(s, g_Kh + ((size_t)b * CC + mbase) * NN + k0, NN,
                    g_Vh + ((size_t)b * CC + nbase) * NN + k0, NN, 512 / 32, acc);

    float* Out = g_ctx[split] + ((size_t)b * CC + mbase) * CC + nbase;
    const int lane = threadIdx.x & 31, warp = threadIdx.x >> 5;
    const int wm = (warp >> 2) * 64, wn = (warp & 3) * 32;
    const int g = lane >> 2, tg = lane & 3;
#pragma unroll
    for (int i = 0; i < 4; i++) {
        const int r0 = wm + 16 * i + g;
#pragma unroll
        for (int j = 0; j < 4; j++) {
            const int col = wn + 8 * j + 2 * tg;
            *(float2*)&Out[(size_t)r0 * CC + col] = make_float2(acc[i][j][0], acc[i][j][1]);
            *(float2*)&Out[(size_t)(r0 + 8) * CC + col] = make_float2(acc[i][j][2], acc[i][j][3]);
        }
    }
}

// ---------------------------------------------------------------------------
// Kernel 5: Wc[b] = wo @ (sum of 8 ctx partials)/4096 -> fp16. SIMT (tiny).
// grid (4, 4, 8), 256 threads, 64x64 tiles.
// ---------------------------------------------------------------------------
__global__ __launch_bounds__(256) void gemm_wc(const float* __restrict__ wo)
{
    __shared__ __align__(16) float As[16][68];
    __shared__ __align__(16) float Bs[16][68];

    const int b = blockIdx.z;
    const int mbase = blockIdx.y * 64;
    const int nbase = blockIdx.x * 64;
    const float* Aptr = wo + mbase * CC;
    const size_t boff = (size_t)b * CC * CC + nbase;

    const int t = threadIdx.x;
    const int tx = t & 15, ty = t >> 4;
    const int arow = t >> 4, acol = t & 15;
    const int bcol = t & 63, brow = t >> 6;

    float acc[4][4] = {};
    for (int k0 = 0; k0 < CC; k0 += 16) {
#pragma unroll
        for (int r = 0; r < 4; r++)
            As[acol][arow + 16 * r] = Aptr[(arow + 16 * r) * CC + k0 + acol];
#pragma unroll
        for (int r = 0; r < 4; r++) {
            const size_t kr = boff + (size_t)(k0 + brow + 4 * r) * CC + bcol;
            float s = 0.f;
#pragma unroll
            for (int p = 0; p < NSPLIT; p++) s += g_ctx[p][kr];
            Bs[brow + 4 * r][bcol] = s * (1.f / 4096.f);
        }
        __syncthreads();
#pragma unroll
        for (int kk = 0; kk < 16; kk++) {
            float4 a4 = *(const float4*)&As[kk][ty * 4];
            float4 b4 = *(const float4*)&Bs[kk][tx * 4];
            float av[4] = {a4.x, a4.y, a4.z, a4.w};
            float bw[4] = {b4.x, b4.y, b4.z, b4.w};
#pragma unroll
            for (int i = 0; i < 4; i++)
#pragma unroll
                for (int j = 0; j < 4; j++) acc[i][j] += av[i] * bw[j];
        }
        __syncthreads();
    }

    half* Out = g_Wch + ((size_t)b * CC + mbase) * CC + nbase;
#pragma unroll
    for (int i = 0; i < 4; i++) {
        *(__half2*)&Out[(ty * 4 + i) * CC + tx * 4]     = __floats2half2_rn(acc[i][0], acc[i][1]);
        *(__half2*)&Out[(ty * 4 + i) * CC + tx * 4 + 2] = __floats2half2_rn(acc[i][2], acc[i][3]);
    }
}

// ---------------------------------------------------------------------------
// Kernel 6: out[b] = Wc[b] @ q_s[b] / 64 + bo.  grid (32, 2, 8), dyn smem
// ---------------------------------------------------------------------------
__global__ __launch_bounds__(256) void gemm_out(const float* __restrict__ bo,
                                                float* __restrict__ out)
{
    extern __shared__ __align__(16) char dyn[];
    SmP<true>* s = reinterpret_cast<SmP<true>*>(dyn);

    const int b = blockIdx.z;
    const int mbase = blockIdx.y * 128;
    const int nbase = blockIdx.x * 128;

    float acc[4][4][4] = {};
    gemm_run<true>(s, g_Wch + (size_t)b * CC * CC + mbase * CC, CC,
                   g_Qh + (size_t)b * CC * NN + nbase, NN, CC / 32, acc);

    constexpr float IS = 1.f / 64.f;
    float* OutB = out + ((size_t)b * CC + mbase) * NN + nbase;
    const int lane = threadIdx.x & 31, warp = threadIdx.x >> 5;
    const int wm = (warp >> 2) * 64, wn = (warp & 3) * 32;
    const int g = lane >> 2, tg = lane & 3;
#pragma unroll
    for (int i = 0; i < 4; i++) {
        const int r0 = wm + 16 * i + g;
        const float b0v = bo[mbase + r0], b1v = bo[mbase + r0 + 8];
#pragma unroll
        for (int j = 0; j < 4; j++) {
            const int col = wn + 8 * j + 2 * tg;
            *(float2*)&OutB[(size_t)r0 * NN + col] =
                make_float2(acc[i][j][0] * IS + b0v, acc[i][j][1] * IS + b0v);
            *(float2*)&OutB[(size_t)(r0 + 8) * NN + col] =
                make_float2(acc[i][j][2] * IS + b1v, acc[i][j][3] * IS + b1v);
        }
    }
}

// ---------------------------------------------------------------------------
extern "C" void kernel_launch(void* const* d_in, const int* in_sizes, int n_in,
                              void* d_out, int out_size)
{
    const float* x    = (const float*)d_in[0];
    const float* cp   = (const float*)d_in[1];
    const float* wq   = (const float*)d_in[2];
    const float* bq   = (const float*)d_in[3];
    const float* wkv  = (const float*)d_in[4];
    const float* bkv  = (const float*)d_in[5];
    const float* wo   = (const float*)d_in[6];
    const float* bo   = (const float*)d_in[7];
    float* out = (float*)d_out;

    const int smA = (int)sizeof(SmP<true>);   // ~56.8 KB
    const int smC = (int)sizeof(SmP<false>);  // ~61.4 KB
    cudaFuncSetAttribute(gemm_qkv, cudaFuncAttributeMaxDynamicSharedMemorySize, smA);
    cudaFuncSetAttribute(gemm_ctx, cudaFuncAttributeMaxDynamicSharedMemorySize, smC);
    cudaFuncSetAttribute(gemm_out, cudaFuncAttributeMaxDynamicSharedMemorySize, smA);

    conv_inputs<<<dim3(4096, 2), 256>>>(x, cp);
    conv_w<<<96, 256>>>(wq, wkv);
    gemm_qkv<<<dim3(32, 6, 8), 256, smA>>>(bq, bkv);
    softmax_k_kernel<<<2048, 256>>>();
    softmax_q_kernel<<<512, 256>>>();
    gemm_ctx<<<dim3(2, 2, 64), 256, smC>>>();
    gemm_wc<<<dim3(4, 4, 8), 256>>>(wo);
    gemm_out<<<dim3(32, 2, 8), 256, smA>>>(bo, out);
}

// round 7
// speedup vs baseline: 4.0133x; 1.0184x over previous
#include <cuda_runtime.h>
#include <cuda_fp16.h>
#include <cstdint>

#define BB 8
#define CC 256
#define NN 4096
#define NSPLIT 8

// Scratch (device globals — no allocation allowed)
__device__ __align__(128) half  g_Xh[BB * CC * NN];          // 16 MB  x in fp16
__device__ __align__(128) half  g_Ch[BB * CC * NN];          // 16 MB  cproj in fp16
__device__ __align__(128) half  g_Wqh[CC * CC];              // wq fp16
__device__ __align__(128) half  g_Wkvh[2 * CC * CC];         // wkv fp16
__device__ __align__(128) half  g_Qh[BB * CC * NN];          // 16 MB  Q logits -> softmax(Q)*64
__device__ __align__(128) half  g_Kh[BB * CC * NN];          // 16 MB  K logits -> softmax(K)*4096
__device__ __align__(128) half  g_Vh[BB * CC * NN];          // 16 MB  V fp16
__device__ __align__(128) float g_ctx[NSPLIT][BB * CC * CC]; // 16 MB  split-K partials
__device__ __align__(128) half  g_Wch[BB * CC * CC];         // 1 MB   wo@ctx fp16

// ---------------------------------------------------------------------------
// helpers
// ---------------------------------------------------------------------------
__device__ __forceinline__ uint32_t smem_u32(const void* p) {
    uint32_t a;
    asm("{ .reg .u64 t; cvta.to.shared.u64 t, %1; cvt.u32.u64 %0, t; }" : "=r"(a) : "l"(p));
    return a;
}
__device__ __forceinline__ void cpa16(uint32_t dst, const void* src) {
    asm volatile("cp.async.cg.shared.global [%0], [%1], 16;" :: "r"(dst), "l"(src));
}
__device__ __forceinline__ void ldmx4(uint32_t* r, uint32_t addr) {
    asm volatile("ldmatrix.sync.aligned.m8n8.x4.shared.b16 {%0,%1,%2,%3}, [%4];"
                 : "=r"(r[0]), "=r"(r[1]), "=r"(r[2]), "=r"(r[3]) : "r"(addr));
}
__device__ __forceinline__ void ldmx4t(uint32_t* r, uint32_t addr) {
    asm volatile("ldmatrix.sync.aligned.m8n8.x4.trans.shared.b16 {%0,%1,%2,%3}, [%4];"
                 : "=r"(r[0]), "=r"(r[1]), "=r"(r[2]), "=r"(r[3]) : "r"(addr));
}
__device__ __forceinline__ void mma16816(float* c, const uint32_t* a, const uint32_t* b) {
    asm volatile(
        "mma.sync.aligned.m16n8k16.row.col.f32.f16.f16.f32 "
        "{%0,%1,%2,%3}, {%4,%5,%6,%7}, {%8,%9}, {%0,%1,%2,%3};"
        : "+f"(c[0]), "+f"(c[1]), "+f"(c[2]), "+f"(c[3])
        : "r"(a[0]), "r"(a[1]), "r"(a[2]), "r"(a[3]), "r"(b[0]), "r"(b[1]));
}
__device__ __forceinline__ uint4 pack8(float4 a, float4 b) {
    uint4 u;
    half2 h;
    h = __floats2half2_rn(a.x, a.y); u.x = *(const uint32_t*)&h;
    h = __floats2half2_rn(a.z, a.w); u.y = *(const uint32_t*)&h;
    h = __floats2half2_rn(b.x, b.y); u.z = *(const uint32_t*)&h;
    h = __floats2half2_rn(b.z, b.w); u.w = *(const uint32_t*)&h;
    return u;
}

// ---------------------------------------------------------------------------
// fp16 cp.async 3-stage GEMM core: C[128x128] += A[128xK] * B
// BKN=false: B [n][ldb] K-major (C = A * B^T);  BKN=true: B [k][ldb], n contig
// 256 threads, 8 warps (2x4), warp tile 64x32, m16n8k16, BK=32, NST=3.
// ---------------------------------------------------------------------------
template <bool BKN>
struct SmP {
    __align__(16) half A[3][128][40];
    __align__(16) half B[3][BKN ? 32 : 128][BKN ? 136 : 40];
};

template <bool BKN>
__device__ __forceinline__ void issue_stage(SmP<BKN>* s, int st,
                                            const half* __restrict__ Asrc, int lda,
                                            const half* __restrict__ Bsrc, int ldb, int t) {
#pragma unroll
    for (int r = 0; r < 2; r++) {
        const int idx = t + 256 * r;
        const int row = idx >> 2, seg = idx & 3;
        cpa16(smem_u32(&s->A[st][row][seg * 8]), Asrc + (size_t)row * lda + seg * 8);
    }
    if (BKN) {
#pragma unroll
        for (int r = 0; r < 2; r++) {
            const int idx = t + 256 * r;
            const int row = idx >> 4, seg = idx & 15;
            cpa16(smem_u32(&s->B[st][row][seg * 8]), Bsrc + (size_t)row * ldb + seg * 8);
        }
    } else {
#pragma unroll
        for (int r = 0; r < 2; r++) {
            const int idx = t + 256 * r;
            const int row = idx >> 2, seg = idx & 3;
            cpa16(smem_u32(&s->B[st][row][seg * 8]), Bsrc + (size_t)row * ldb + seg * 8);
        }
    }
}

template <bool BKN>
__device__ __forceinline__ void compute(SmP<BKN>* s, int buf, float acc[4][4][4],
                                        int wm, int wn, int lane) {
#pragma unroll
    for (int ks = 0; ks < 32; ks += 16) {
        uint32_t af[4][4];
#pragma unroll
        for (int mi = 0; mi < 4; mi++)
            ldmx4(af[mi],
                  smem_u32(&s->A[buf][wm + 16 * mi + (lane & 15)][ks + ((lane >> 4) << 3)]));
        uint32_t bf[4][2];
#pragma unroll
        for (int nj2 = 0; nj2 < 2; nj2++) {
            uint32_t r[4];
            if (BKN)
                ldmx4t(r, smem_u32(&s->B[buf][ks + (((lane >> 3) & 1) << 3) + (lane & 7)]
                                          [wn + nj2 * 16 + ((lane >> 4) << 3)]));
            else
                ldmx4(r, smem_u32(&s->B[buf][wn + nj2 * 16 + ((lane >> 4) << 3) + (lane & 7)]
                                         [ks + (((lane >> 3) & 1) << 3)]));
            bf[2 * nj2][0] = r[0]; bf[2 * nj2][1] = r[1];
            bf[2 * nj2 + 1][0] = r[2]; bf[2 * nj2 + 1][1] = r[3];
        }
#pragma unroll
        for (int mi = 0; mi < 4; mi++)
#pragma unroll
            for (int nj = 0; nj < 4; nj++)
                mma16816(acc[mi][nj], af[mi], bf[nj]);
    }
}

template <bool BKN>
__device__ __forceinline__ void gemm_run(SmP<BKN>* s, const half* __restrict__ A, int lda,
                                         const half* __restrict__ B, int ldb,
                                         int nIter, float acc[4][4][4]) {
    const int t = threadIdx.x, lane = t & 31, warp = t >> 5;
    const int wm = (warp >> 2) * 64, wn = (warp & 3) * 32;

#pragma unroll
    for (int st = 0; st < 2; st++) {
        if (st < nIter)
            issue_stage<BKN>(s, st, A + st * 32, lda,
                             BKN ? B + (size_t)st * 32 * ldb : B + st * 32, ldb, t);
        asm volatile("cp.async.commit_group;" ::: "memory");
    }
    int cur = 0;
    for (int it = 0; it < nIter; ++it) {
        asm volatile("cp.async.wait_group 1;" ::: "memory");
        __syncthreads();
        compute<BKN>(s, cur, acc, wm, wn, lane);
        const int nxt = it + 2;
        if (nxt < nIter) {
            int nst = cur + 2; if (nst >= 3) nst -= 3;
            issue_stage<BKN>(s, nst, A + nxt * 32, lda,
                             BKN ? B + (size_t)nxt * 32 * ldb : B + nxt * 32, ldb, t);
        }
        asm volatile("cp.async.commit_group;" ::: "memory");
        if (++cur == 3) cur = 0;
    }
}

// ---------------------------------------------------------------------------
// Kernel 0a: convert x / cproj -> fp16.  grid (4096, 2), 256 thr, 8 elems/thr
// ---------------------------------------------------------------------------
__global__ __launch_bounds__(256) void conv_inputs(const float* __restrict__ x,
                                                   const float* __restrict__ cp)
{
    const int gid = blockIdx.x * 256 + threadIdx.x;
    const float* src = blockIdx.y ? cp : x;
    half* dst = blockIdx.y ? g_Ch : g_Xh;
    const size_t o = (size_t)gid * 8;
    float4 a = *(const float4*)(src + o);
    float4 b = *(const float4*)(src + o + 4);
    *(uint4*)(dst + o) = pack8(a, b);
}

// Kernel 0b: convert wq, wkv -> fp16.  grid 96, 256 thr, 8 elems/thr
__global__ __launch_bounds__(256) void conv_w(const float* __restrict__ wq,
                                              const float* __restrict__ wkv)
{
    const size_t o = (size_t)(blockIdx.x * 256 + threadIdx.x) * 8;
    const float* src;
    half* dst;
    size_t oo;
    if (o < CC * CC) { src = wq;  dst = g_Wqh;  oo = o; }
    else             { src = wkv; dst = g_Wkvh; oo = o - CC * CC; }
    float4 a = *(const float4*)(src + oo);
    float4 b = *(const float4*)(src + oo + 4);
    *(uint4*)(dst + oo) = pack8(a, b);
}

// ---------------------------------------------------------------------------
// Kernel 1: Q/K logits + V, all fp16 outputs.
// y 0..1: Q -> g_Qh;  y 2..3: K -> g_Kh;  y 4..5: V -> g_Vh
// grid (32, 6, 8), 256 threads, dynamic smem
// ---------------------------------------------------------------------------
__global__ __launch_bounds__(256) void gemm_qkv(
    const float* __restrict__ bq, const float* __restrict__ bkv)
{
    extern __shared__ __align__(16) char dyn[];
    SmP<true>* s = reinterpret_cast<SmP<true>*>(dyn);

    const int b = blockIdx.z;
    const int nbase = blockIdx.x * 128;
    const int yb = blockIdx.y;

    const half* W;
    const half* X;
    const float* bias;
    half* OutH;
    if (yb < 2) {
        W = g_Wqh + yb * 128 * CC; X = g_Xh; bias = bq + yb * 128;
        OutH = g_Qh + ((size_t)b * CC + yb * 128) * NN;
    } else {
        const int r = (yb - 2) * 128;
        W = g_Wkvh + r * CC; X = g_Ch; bias = bkv + r;
        if (r < CC) OutH = g_Kh + ((size_t)b * CC + r) * NN;
        else        OutH = g_Vh + ((size_t)b * CC + (r - CC)) * NN;
    }

    float acc[4][4][4] = {};
    gemm_run<true>(s, W, CC, X + (size_t)b * CC * NN + nbase, NN, CC / 32, acc);

    const int lane = threadIdx.x & 31, warp = threadIdx.x >> 5;
    const int wm = (warp >> 2) * 64, wn = (warp & 3) * 32;
    const int g = lane >> 2, tg = lane & 3;
#pragma unroll
    for (int i = 0; i < 4; i++) {
        const int r0 = wm + 16 * i + g;
        const float b0v = bias[r0], b1v = bias[r0 + 8];
#pragma unroll
        for (int j = 0; j < 4; j++) {
            const int col = nbase + wn + 8 * j + 2 * tg;
            *(__half2*)&OutH[(size_t)r0 * NN + col] =
                __floats2half2_rn(acc[i][j][0] + b0v, acc[i][j][1] + b0v);
            *(__half2*)&OutH[(size_t)(r0 + 8) * NN + col] =
                __floats2half2_rn(acc[i][j][2] + b1v, acc[i][j][3] + b1v);
        }
    }
}

// ---------------------------------------------------------------------------
// Kernel 2: softmax over N=4096 rows of g_Kh, in place, x4096. half2 I/O.
// ---------------------------------------------------------------------------
__global__ __launch_bounds__(256) void softmax_k_kernel()
{
    __half2* p = (__half2*)(g_Kh + (size_t)blockIdx.x * NN);  // 2048 half2
    const int t = threadIdx.x;
    __shared__ float sh[8];

    float2 v[8];
    float m = -1e30f;
#pragma unroll
    for (int i = 0; i < 8; i++) {
        v[i] = __half22float2(p[t + 256 * i]);
        m = fmaxf(m, fmaxf(v[i].x, v[i].y));
    }
#pragma unroll
    for (int o = 16; o; o >>= 1) m = fmaxf(m, __shfl_xor_sync(0xffffffffu, m, o));
    if ((t & 31) == 0) sh[t >> 5] = m;
    __syncthreads();
    m = sh[0];
#pragma unroll
    for (int i = 1; i < 8; i++) m = fmaxf(m, sh[i]);

    float s = 0.f;
#pragma unroll
    for (int i = 0; i < 8; i++) {
        v[i].x = __expf(v[i].x - m);
        v[i].y = __expf(v[i].y - m);
        s += v[i].x + v[i].y;
    }
#pragma unroll
    for (int o = 16; o; o >>= 1) s += __shfl_xor_sync(0xffffffffu, s, o);
    __syncthreads();
    if ((t & 31) == 0) sh[t >> 5] = s;
    __syncthreads();
    s = 0.f;
#pragma unroll
    for (int i = 0; i < 8; i++) s += sh[i];

    const float inv = 4096.f / s;
#pragma unroll
    for (int i = 0; i < 8; i++)
        p[t + 256 * i] = __floats2half2_rn(v[i].x * inv, v[i].y * inv);
}

// ---------------------------------------------------------------------------
// Kernel 3: softmax over d=64 of 0.25*Q on g_Qh, in place, x64.
// ---------------------------------------------------------------------------
__global__ __launch_bounds__(256) void softmax_q_kernel()
{
    const int idx = blockIdx.x * 256 + threadIdx.x;
    const int n = idx & (NN - 1);
    const int bh = idx >> 12;
    half* base = g_Qh + (size_t)bh * 64 * NN + n;

    float v[64];
    float m = -1e30f;
#pragma unroll
    for (int d = 0; d < 64; d++) { v[d] = __half2float(base[d * NN]); m = fmaxf(m, v[d]); }
    float s = 0.f;
#pragma unroll
    for (int d = 0; d < 64; d++) { v[d] = __expf((v[d] - m) * 0.25f); s += v[d]; }
    const float inv = 64.f / s;
#pragma unroll
    for (int d = 0; d < 64; d++) base[d * NN] = __float2half(v[d] * inv);
}

// ---------------------------------------------------------------------------
// Kernel 4: ctx partial (x4096) = k_s-tile @ V-tile^T over split n-range.
// grid (2, 2, 64): z = b*8 + split, K=512 per split.  dynamic smem
// ---------------------------------------------------------------------------
__global__ __launch_bounds__(256) void gemm_ctx()
{
    extern __shared__ __align__(16) char dyn[];
    SmP<false>* s = reinterpret_cast<SmP<false>*>(dyn);

    const int split = blockIdx.z & 7;
    const int b = blockIdx.z >> 3;
    const int mbase = blockIdx.y * 128;
    const int nbase = blockIdx.x * 128;
    const int k0 = split * 512;

    float acc[4][4][4] = {};
    gemm_run<false>(s, g_Kh + ((size_t)b * CC + mbase) * NN + k0, NN,
                    g_Vh + ((size_t)b * CC + nbase) * NN + k0, NN, 512 / 32, acc);

    float* Out = g_ctx[split] + ((size_t)b * CC + mbase) * CC + nbase;
    const int lane = threadIdx.x & 31, warp = threadIdx.x >> 5;
    const int wm = (warp >> 2) * 64, wn = (warp & 3) * 32;
    const int g = lane >> 2, tg = lane & 3;
#pragma unroll
    for (int i = 0; i < 4; i++) {
        const int r0 = wm + 16 * i + g;
#pragma unroll
        for (int j = 0; j < 4; j++) {
            const int col = wn + 8 * j + 2 * tg;
            *(float2*)&Out[(size_t)r0 * CC + col] = make_float2(acc[i][j][0], acc[i][j][1]);
            *(float2*)&Out[(size_t)(r0 + 8) * CC + col] = make_float2(acc[i][j][2], acc[i][j][3]);
        }
    }
}

// ---------------------------------------------------------------------------
// Kernel 5: Wc[b] = wo @ (sum of 8 ctx partials)/4096 -> fp16. SIMT (tiny).
// grid (4, 4, 8), 256 threads, 64x64 tiles.
// ---------------------------------------------------------------------------
__global__ __launch_bounds__(256) void gemm_wc(const float* __restrict__ wo)
{
    __shared__ __align__(16) float As[16][68];
    __shared__ __align__(16) float Bs[16][68];

    const int b = blockIdx.z;
    const int mbase = blockIdx.y * 64;
    const int nbase = blockIdx.x * 64;
    const float* Aptr = wo + mbase * CC;
    const size_t boff = (size_t)b * CC * CC + nbase;

    const int t = threadIdx.x;
    const int tx = t & 15, ty = t >> 4;
    const int arow = t >> 4, acol = t & 15;
    const int bcol = t & 63, brow = t >> 6;

    float acc[4][4] = {};
    for (int k0 = 0; k0 < CC; k0 += 16) {
#pragma unroll
        for (int r = 0; r < 4; r++)
            As[acol][arow + 16 * r] = Aptr[(arow + 16 * r) * CC + k0 + acol];
#pragma unroll
        for (int r = 0; r < 4; r++) {
            const size_t kr = boff + (size_t)(k0 + brow + 4 * r) * CC + bcol;
            float s = 0.f;
#pragma unroll
            for (int p = 0; p < NSPLIT; p++) s += g_ctx[p][kr];
            Bs[brow + 4 * r][bcol] = s * (1.f / 4096.f);
        }
        __syncthreads();
#pragma unroll
        for (int kk = 0; kk < 16; kk++) {
            float4 a4 = *(const float4*)&As[kk][ty * 4];
            float4 b4 = *(const float4*)&Bs[kk][tx * 4];
            float av[4] = {a4.x, a4.y, a4.z, a4.w};
            float bw[4] = {b4.x, b4.y, b4.z, b4.w};
#pragma unroll
            for (int i = 0; i < 4; i++)
#pragma unroll
                for (int j = 0; j < 4; j++) acc[i][j] += av[i] * bw[j];
        }
        __syncthreads();
    }

    half* Out = g_Wch + ((size_t)b * CC + mbase) * CC + nbase;
#pragma unroll
    for (int i = 0; i < 4; i++) {
        *(__half2*)&Out[(ty * 4 + i) * CC + tx * 4]     = __floats2half2_rn(acc[i][0], acc[i][1]);
        *(__half2*)&Out[(ty * 4 + i) * CC + tx * 4 + 2] = __floats2half2_rn(acc[i][2], acc[i][3]);
    }
}

// ---------------------------------------------------------------------------
// Kernel 6: out[b] = Wc[b] @ q_s[b] / 64 + bo.  grid (32, 2, 8), dyn smem
// ---------------------------------------------------------------------------
__global__ __launch_bounds__(256) void gemm_out(const float* __restrict__ bo,
                                                float* __restrict__ out)
{
    extern __shared__ __align__(16) char dyn[];
    SmP<true>* s = reinterpret_cast<SmP<true>*>(dyn);

    const int b = blockIdx.z;
    const int mbase = blockIdx.y * 128;
    const int nbase = blockIdx.x * 128;

    float acc[4][4][4] = {};
    gemm_run<true>(s, g_Wch + (size_t)b * CC * CC + mbase * CC, CC,
                   g_Qh + (size_t)b * CC * NN + nbase, NN, CC / 32, acc);

    constexpr float IS = 1.f / 64.f;
    float* OutB = out + ((size_t)b * CC + mbase) * NN + nbase;
    const int lane = threadIdx.x & 31, warp = threadIdx.x >> 5;
    const int wm = (warp >> 2) * 64, wn = (warp & 3) * 32;
    const int g = lane >> 2, tg = lane & 3;
#pragma unroll
    for (int i = 0; i < 4; i++) {
        const int r0 = wm + 16 * i + g;
        const float b0v = bo[mbase + r0], b1v = bo[mbase + r0 + 8];
#pragma unroll
        for (int j = 0; j < 4; j++) {
            const int col = wn + 8 * j + 2 * tg;
            *(float2*)&OutB[(size_t)r0 * NN + col] =
                make_float2(acc[i][j][0] * IS + b0v, acc[i][j][1] * IS + b0v);
            *(float2*)&OutB[(size_t)(r0 + 8) * NN + col] =
                make_float2(acc[i][j][2] * IS + b1v, acc[i][j][3] * IS + b1v);
        }
    }
}

// ---------------------------------------------------------------------------
extern "C" void kernel_launch(void* const* d_in, const int* in_sizes, int n_in,
                              void* d_out, int out_size)
{
    const float* x    = (const float*)d_in[0];
    const float* cp   = (const float*)d_in[1];
    const float* wq   = (const float*)d_in[2];
    const float* bq   = (const float*)d_in[3];
    const float* wkv  = (const float*)d_in[4];
    const float* bkv  = (const float*)d_in[5];
    const float* wo   = (const float*)d_in[6];
    const float* bo   = (const float*)d_in[7];
    float* out = (float*)d_out;

    const int smA = (int)sizeof(SmP<true>);   // ~56.8 KB
    const int smC = (int)sizeof(SmP<false>);  // ~61.4 KB
    cudaFuncSetAttribute(gemm_qkv, cudaFuncAttributeMaxDynamicSharedMemorySize, smA);
    cudaFuncSetAttribute(gemm_ctx, cudaFuncAttributeMaxDynamicSharedMemorySize, smC);
    cudaFuncSetAttribute(gemm_out, cudaFuncAttributeMaxDynamicSharedMemorySize, smA);

    conv_inputs<<<dim3(4096, 2), 256>>>(x, cp);
    conv_w<<<96, 256>>>(wq, wkv);
    gemm_qkv<<<dim3(32, 6, 8), 256, smA>>>(bq, bkv);
    softmax_k_kernel<<<2048, 256>>>();
    softmax_q_kernel<<<512, 256>>>();
    gemm_ctx<<<dim3(2, 2, 64), 256, smC>>>();
    gemm_wc<<<dim3(4, 4, 8), 256>>>(wo);
    gemm_out<<<dim3(32, 2, 8), 256, smA>>>(bo, out);
}

// round 10
// speedup vs baseline: 4.1053x; 1.0229x over previous
#include <cuda_runtime.h>
#include <cuda_fp16.h>
#include <cstdint>

#define BB 8
#define CC 256
#define NN 4096
#define NSPLIT 8

// Scratch (device globals — no allocation allowed)
__device__ __align__(128) half  g_Xh[BB * CC * NN];          // 16 MB  x in fp16
__device__ __align__(128) half  g_Ch[BB * CC * NN];          // 16 MB  cproj in fp16
__device__ __align__(128) half  g_Wqh[CC * CC];              // wq fp16
__device__ __align__(128) half  g_Wkvh[2 * CC * CC];         // wkv fp16
__device__ __align__(128) half  g_Qh[BB * CC * NN];          // 16 MB  Q logits -> softmax(Q)*64
__device__ __align__(128) half  g_Kh[BB * CC * NN];          // 16 MB  K logits -> softmax(K)*4096
__device__ __align__(128) half  g_Vh[BB * CC * NN];          // 16 MB  V fp16
__device__ __align__(128) half  g_ctxh[NSPLIT][BB * CC * CC];// 8 MB   split-K partials fp16
__device__ __align__(128) half  g_Wch[BB * CC * CC];         // 1 MB   wo@ctx fp16

// ---------------------------------------------------------------------------
// helpers
// ---------------------------------------------------------------------------
__device__ __forceinline__ uint32_t smem_u32(const void* p) {
    uint32_t a;
    asm("{ .reg .u64 t; cvta.to.shared.u64 t, %1; cvt.u32.u64 %0, t; }" : "=r"(a) : "l"(p));
    return a;
}
__device__ __forceinline__ void cpa16(uint32_t dst, const void* src) {
    asm volatile("cp.async.cg.shared.global [%0], [%1], 16;" :: "r"(dst), "l"(src));
}
__device__ __forceinline__ void ldmx4(uint32_t* r, uint32_t addr) {
    asm volatile("ldmatrix.sync.aligned.m8n8.x4.shared.b16 {%0,%1,%2,%3}, [%4];"
                 : "=r"(r[0]), "=r"(r[1]), "=r"(r[2]), "=r"(r[3]) : "r"(addr));
}
__device__ __forceinline__ void ldmx4t(uint32_t* r, uint32_t addr) {
    asm volatile("ldmatrix.sync.aligned.m8n8.x4.trans.shared.b16 {%0,%1,%2,%3}, [%4];"
                 : "=r"(r[0]), "=r"(r[1]), "=r"(r[2]), "=r"(r[3]) : "r"(addr));
}
__device__ __forceinline__ void mma16816(float* c, const uint32_t* a, const uint32_t* b) {
    asm volatile(
        "mma.sync.aligned.m16n8k16.row.col.f32.f16.f16.f32 "
        "{%0,%1,%2,%3}, {%4,%5,%6,%7}, {%8,%9}, {%0,%1,%2,%3};"
        : "+f"(c[0]), "+f"(c[1]), "+f"(c[2]), "+f"(c[3])
        : "r"(a[0]), "r"(a[1]), "r"(a[2]), "r"(a[3]), "r"(b[0]), "r"(b[1]));
}
__device__ __forceinline__ uint4 pack8(float4 a, float4 b) {
    uint4 u;
    half2 h;
    h = __floats2half2_rn(a.x, a.y); u.x = *(const uint32_t*)&h;
    h = __floats2half2_rn(a.z, a.w); u.y = *(const uint32_t*)&h;
    h = __floats2half2_rn(b.x, b.y); u.z = *(const uint32_t*)&h;
    h = __floats2half2_rn(b.z, b.w); u.w = *(const uint32_t*)&h;
    return u;
}

// ---------------------------------------------------------------------------
// fp16 cp.async 3-stage GEMM core: C[128x128] += A[128xK] * B
// BKN=false: B [n][ldb] K-major (C = A * B^T);  BKN=true: B [k][ldb], n contig
// 256 threads, 8 warps (2x4), warp tile 64x32, m16n8k16, BK=32, NST=3.
// ---------------------------------------------------------------------------
template <bool BKN>
struct SmP {
    __align__(16) half A[3][128][40];
    __align__(16) half B[3][BKN ? 32 : 128][BKN ? 136 : 40];
};

template <bool BKN>
__device__ __forceinline__ void issue_stage(SmP<BKN>* s, int st,
                                            const half* __restrict__ Asrc, int lda,
                                            const half* __restrict__ Bsrc, int ldb, int t) {
#pragma unroll
    for (int r = 0; r < 2; r++) {
        const int idx = t + 256 * r;
        const int row = idx >> 2, seg = idx & 3;
        cpa16(smem_u32(&s->A[st][row][seg * 8]), Asrc + (size_t)row * lda + seg * 8);
    }
    if (BKN) {
#pragma unroll
        for (int r = 0; r < 2; r++) {
            const int idx = t + 256 * r;
            const int row = idx >> 4, seg = idx & 15;
            cpa16(smem_u32(&s->B[st][row][seg * 8]), Bsrc + (size_t)row * ldb + seg * 8);
        }
    } else {
#pragma unroll
        for (int r = 0; r < 2; r++) {
            const int idx = t + 256 * r;
            const int row = idx >> 2, seg = idx & 3;
            cpa16(smem_u32(&s->B[st][row][seg * 8]), Bsrc + (size_t)row * ldb + seg * 8);
        }
    }
}

template <bool BKN>
__device__ __forceinline__ void compute(SmP<BKN>* s, int buf, float acc[4][4][4],
                                        int wm, int wn, int lane) {
#pragma unroll
    for (int ks = 0; ks < 32; ks += 16) {
        uint32_t af[4][4];
#pragma unroll
        for (int mi = 0; mi < 4; mi++)
            ldmx4(af[mi],
                  smem_u32(&s->A[buf][wm + 16 * mi + (lane & 15)][ks + ((lane >> 4) << 3)]));
        uint32_t bf[4][2];
#pragma unroll
        for (int nj2 = 0; nj2 < 2; nj2++) {
            uint32_t r[4];
            if (BKN)
                ldmx4t(r, smem_u32(&s->B[buf][ks + (((lane >> 3) & 1) << 3) + (lane & 7)]
                                          [wn + nj2 * 16 + ((lane >> 4) << 3)]));
            else
                ldmx4(r, smem_u32(&s->B[buf][wn + nj2 * 16 + ((lane >> 4) << 3) + (lane & 7)]
                                         [ks + (((lane >> 3) & 1) << 3)]));
            bf[2 * nj2][0] = r[0]; bf[2 * nj2][1] = r[1];
            bf[2 * nj2 + 1][0] = r[2]; bf[2 * nj2 + 1][1] = r[3];
        }
#pragma unroll
        for (int mi = 0; mi < 4; mi++)
#pragma unroll
            for (int nj = 0; nj < 4; nj++)
                mma16816(acc[mi][nj], af[mi], bf[nj]);
    }
}

template <bool BKN>
__device__ __forceinline__ void gemm_run(SmP<BKN>* s, const half* __restrict__ A, int lda,
                                         const half* __restrict__ B, int ldb,
                                         int nIter, float acc[4][4][4]) {
    const int t = threadIdx.x, lane = t & 31, warp = t >> 5;
    const int wm = (warp >> 2) * 64, wn = (warp & 3) * 32;

#pragma unroll
    for (int st = 0; st < 2; st++) {
        if (st < nIter)
            issue_stage<BKN>(s, st, A + st * 32, lda,
                             BKN ? B + (size_t)st * 32 * ldb : B + st * 32, ldb, t);
        asm volatile("cp.async.commit_group;" ::: "memory");
    }
    int cur = 0;
    for (int it = 0; it < nIter; ++it) {
        asm volatile("cp.async.wait_group 1;" ::: "memory");
        __syncthreads();
        compute<BKN>(s, cur, acc, wm, wn, lane);
        const int nxt = it + 2;
        if (nxt < nIter) {
            int nst = cur + 2; if (nst >= 3) nst -= 3;
            issue_stage<BKN>(s, nst, A + nxt * 32, lda,
                             BKN ? B + (size_t)nxt * 32 * ldb : B + nxt * 32, ldb, t);
        }
        asm volatile("cp.async.commit_group;" ::: "memory");
        if (++cur == 3) cur = 0;
    }
}

// ---------------------------------------------------------------------------
// Kernel 0: convert x / cproj / wq / wkv -> fp16 in one launch.
// grid 8288: [0,4096) x, [4096,8192) cproj, [8192,8288) weights
// ---------------------------------------------------------------------------
__global__ __launch_bounds__(256) void conv_all(const float* __restrict__ x,
                                                const float* __restrict__ cp,
                                                const float* __restrict__ wq,
                                                const float* __restrict__ wkv)
{
    const int bid = blockIdx.x;
    if (bid < 8192) {
        const float* src = (bid < 4096) ? x : cp;
        half* dst = (bid < 4096) ? g_Xh : g_Ch;
        const int lb = bid & 4095;
        const size_t o = ((size_t)lb * 256 + threadIdx.x) * 8;
        float4 a = *(const float4*)(src + o);
        float4 b = *(const float4*)(src + o + 4);
        *(uint4*)(dst + o) = pack8(a, b);
    } else {
        const size_t o = (size_t)((bid - 8192) * 256 + threadIdx.x) * 8;
        const float* src;
        half* dst;
        size_t oo;
        if (o < CC * CC) { src = wq;  dst = g_Wqh;  oo = o; }
        else             { src = wkv; dst = g_Wkvh; oo = o - CC * CC; }
        float4 a = *(const float4*)(src + oo);
        float4 b = *(const float4*)(src + oo + 4);
        *(uint4*)(dst + oo) = pack8(a, b);
    }
}

// ---------------------------------------------------------------------------
// Kernel 1: Q/K logits + V, all fp16 outputs.
// y 0..1: Q -> g_Qh;  y 2..3: K -> g_Kh;  y 4..5: V -> g_Vh
// grid (32, 6, 8), 256 threads, dynamic smem
// ---------------------------------------------------------------------------
__global__ __launch_bounds__(256, 2) void gemm_qkv(
    const float* __restrict__ bq, const float* __restrict__ bkv)
{
    extern __shared__ __align__(16) char dyn[];
    SmP<true>* s = reinterpret_cast<SmP<true>*>(dyn);

    const int b = blockIdx.z;
    const int nbase = blockIdx.x * 128;
    const int yb = blockIdx.y;

    const half* W;
    const half* X;
    const float* bias;
    half* OutH;
    if (yb < 2) {
        W = g_Wqh + yb * 128 * CC; X = g_Xh; bias = bq + yb * 128;
        OutH = g_Qh + ((size_t)b * CC + yb * 128) * NN;
    } else {
        const int r = (yb - 2) * 128;
        W = g_Wkvh + r * CC; X = g_Ch; bias = bkv + r;
        if (r < CC) OutH = g_Kh + ((size_t)b * CC + r) * NN;
        else        OutH = g_Vh + ((size_t)b * CC + (r - CC)) * NN;
    }

    float acc[4][4][4] = {};
    gemm_run<true>(s, W, CC, X + (size_t)b * CC * NN + nbase, NN, CC / 32, acc);

    const int lane = threadIdx.x & 31, warp = threadIdx.x >> 5;
    const int wm = (warp >> 2) * 64, wn = (warp & 3) * 32;
    const int g = lane >> 2, tg = lane & 3;
#pragma unroll
    for (int i = 0; i < 4; i++) {
        const int r0 = wm + 16 * i + g;
        const float b0v = bias[r0], b1v = bias[r0 + 8];
#pragma unroll
        for (int j = 0; j < 4; j++) {
            const int col = nbase + wn + 8 * j + 2 * tg;
            *(__half2*)&OutH[(size_t)r0 * NN + col] =
                __floats2half2_rn(acc[i][j][0] + b0v, acc[i][j][1] + b0v);
            *(__half2*)&OutH[(size_t)(r0 + 8) * NN + col] =
                __floats2half2_rn(acc[i][j][2] + b1v, acc[i][j][3] + b1v);
        }
    }
}

// ---------------------------------------------------------------------------
// Kernel 2: merged softmaxes.
// blocks [0,2048): softmax over N=4096 rows of g_Kh in place, x4096 (half2 I/O)
// blocks [2048,2560): softmax over d=64 of 0.25*Q on g_Qh in place, x64
// ---------------------------------------------------------------------------
__global__ __launch_bounds__(256) void softmax_all()
{
    const int bid = blockIdx.x;
    const int t = threadIdx.x;
    if (bid < 2048) {
        __half2* p = (__half2*)(g_Kh + (size_t)bid * NN);  // 2048 half2
        __shared__ float sh[8];

        float2 v[8];
        float m = -1e30f;
#pragma unroll
        for (int i = 0; i < 8; i++) {
            v[i] = __half22float2(p[t + 256 * i]);
            m = fmaxf(m, fmaxf(v[i].x, v[i].y));
        }
#pragma unroll
        for (int o = 16; o; o >>= 1) m = fmaxf(m, __shfl_xor_sync(0xffffffffu, m, o));
        if ((t & 31) == 0) sh[t >> 5] = m;
        __syncthreads();
        m = sh[0];
#pragma unroll
        for (int i = 1; i < 8; i++) m = fmaxf(m, sh[i]);

        float s = 0.f;
#pragma unroll
        for (int i = 0; i < 8; i++) {
            v[i].x = __expf(v[i].x - m);
            v[i].y = __expf(v[i].y - m);
            s += v[i].x + v[i].y;
        }
#pragma unroll
        for (int o = 16; o; o >>= 1) s += __shfl_xor_sync(0xffffffffu, s, o);
        __syncthreads();
        if ((t & 31) == 0) sh[t >> 5] = s;
        __syncthreads();
        s = 0.f;
#pragma unroll
        for (int i = 0; i < 8; i++) s += sh[i];

        const float inv = 4096.f / s;
#pragma unroll
        for (int i = 0; i < 8; i++)
            p[t + 256 * i] = __floats2half2_rn(v[i].x * inv, v[i].y * inv);
    } else {
        const int idx = (bid - 2048) * 256 + t;
        const int n = idx & (NN - 1);
        const int bh = idx >> 12;
        half* base = g_Qh + (size_t)bh * 64 * NN + n;

        float v[64];
        float m = -1e30f;
#pragma unroll
        for (int d = 0; d < 64; d++) { v[d] = __half2float(base[d * NN]); m = fmaxf(m, v[d]); }
        float s = 0.f;
#pragma unroll
        for (int d = 0; d < 64; d++) { v[d] = __expf((v[d] - m) * 0.25f); s += v[d]; }
        const float inv = 64.f / s;
#pragma unroll
        for (int d = 0; d < 64; d++) base[d * NN] = __float2half(v[d] * inv);
    }
}

// ---------------------------------------------------------------------------
// Kernel 3: ctx partial (x4096, fp16) = k_s-tile @ V-tile^T over split n-range.
// grid (2, 2, 64): z = b*8 + split, K=512 per split.  dynamic smem
// ---------------------------------------------------------------------------
__global__ __launch_bounds__(256, 2) void gemm_ctx()
{
    extern __shared__ __align__(16) char dyn[];
    SmP<false>* s = reinterpret_cast<SmP<false>*>(dyn);

    const int split = blockIdx.z & 7;
    const int b = blockIdx.z >> 3;
    const int mbase = blockIdx.y * 128;
    const int nbase = blockIdx.x * 128;
    const int k0 = split * 512;

    float acc[4][4][4] = {};
    gemm_run<false>(s, g_Kh + ((size_t)b * CC + mbase) * NN + k0, NN,
                    g_Vh + ((size_t)b * CC + nbase) * NN + k0, NN, 512 / 32, acc);

    half* Out = g_ctxh[split] + ((size_t)b * CC + mbase) * CC + nbase;
    const int lane = threadIdx.x & 31, warp = threadIdx.x >> 5;
    const int wm = (warp >> 2) * 64, wn = (warp & 3) * 32;
    const int g = lane >> 2, tg = lane & 3;
#pragma unroll
    for (int i = 0; i < 4; i++) {
        const int r0 = wm + 16 * i + g;
#pragma unroll
        for (int j = 0; j < 4; j++) {
            const int col = wn + 8 * j + 2 * tg;
            *(__half2*)&Out[(size_t)r0 * CC + col] =
                __floats2half2_rn(acc[i][j][0], acc[i][j][1]);
            *(__half2*)&Out[(size_t)(r0 + 8) * CC + col] =
                __floats2half2_rn(acc[i][j][2], acc[i][j][3]);
        }
    }
}

// ---------------------------------------------------------------------------
// Kernel 4: Wc[b] = wo @ (sum of 8 fp16 ctx partials)/4096 -> fp16. SIMT.
// grid (4, 4, 8), 256 threads, 64x64 tiles.
// ---------------------------------------------------------------------------
__global__ __launch_bounds__(256) void gemm_wc(const float* __restrict__ wo)
{
    __shared__ __align__(16) float As[16][68];
    __shared__ __align__(16) float Bs[16][68];

    const int b = blockIdx.z;
    const int mbase = blockIdx.y * 64;
    const int nbase = blockIdx.x * 64;
    const float* Aptr = wo + mbase * CC;
    const size_t boff = (size_t)b * CC * CC + nbase;

    const int t = threadIdx.x;
    const int tx = t & 15, ty = t >> 4;
    const int arow = t >> 4, acol = t & 15;
    const int bcol = t & 63, brow = t >> 6;

    float acc[4][4] = {};
    for (int k0 = 0; k0 < CC; k0 += 16) {
#pragma unroll
        for (int r = 0; r < 4; r++)
            As[acol][arow + 16 * r] = Aptr[(arow + 16 * r) * CC + k0 + acol];
#pragma unroll
        for (int r = 0; r < 4; r++) {
            const size_t kr = boff + (size_t)(k0 + brow + 4 * r) * CC + bcol;
            float s = 0.f;
#pragma unroll
            for (int p = 0; p < NSPLIT; p++) s += __half2float(g_ctxh[p][kr]);
            Bs[brow + 4 * r][bcol] = s * (1.f / 4096.f);
        }
        __syncthreads();
#pragma unroll
        for (int kk = 0; kk < 16; kk++) {
            float4 a4 = *(const float4*)&As[kk][ty * 4];
            float4 b4 = *(const float4*)&Bs[kk][tx * 4];
            float av[4] = {a4.x, a4.y, a4.z, a4.w};
            float bw[4] = {b4.x, b4.y, b4.z, b4.w};
#pragma unroll
            for (int i = 0; i < 4; i++)
#pragma unroll
                for (int j = 0; j < 4; j++) acc[i][j] += av[i] * bw[j];
        }
        __syncthreads();
    }

    half* Out = g_Wch + ((size_t)b * CC + mbase) * CC + nbase;
#pragma unroll
    for (int i = 0; i < 4; i++) {
        *(__half2*)&Out[(ty * 4 + i) * CC + tx * 4]     = __floats2half2_rn(acc[i][0], acc[i][1]);
        *(__half2*)&Out[(ty * 4 + i) * CC + tx * 4 + 2] = __floats2half2_rn(acc[i][2], acc[i][3]);
    }
}

// ---------------------------------------------------------------------------
// Kernel 5: out[b] = Wc[b] @ q_s[b] / 64 + bo.  grid (32, 2, 8), dyn smem
// ---------------------------------------------------------------------------
__global__ __launch_bounds__(256, 2) void gemm_out(const float* __restrict__ bo,
                                                   float* __restrict__ out)
{
    extern __shared__ __align__(16) char dyn[];
    SmP<true>* s = reinterpret_cast<SmP<true>*>(dyn);

    const int b = blockIdx.z;
    const int mbase = blockIdx.y * 128;
    const int nbase = blockIdx.x * 128;

    float acc[4][4][4] = {};
    gemm_run<true>(s, g_Wch + (size_t)b * CC * CC + mbase * CC, CC,
                   g_Qh + (size_t)b * CC * NN + nbase, NN, CC / 32, acc);

    constexpr float IS = 1.f / 64.f;
    float* OutB = out + ((size_t)b * CC + mbase) * NN + nbase;
    const int lane = threadIdx.x & 31, warp = threadIdx.x >> 5;
    const int wm = (warp >> 2) * 64, wn = (warp & 3) * 32;
    const int g = lane >> 2, tg = lane & 3;
#pragma unroll
    for (int i = 0; i < 4; i++) {
        const int r0 = wm + 16 * i + g;
        const float b0v = bo[mbase + r0], b1v = bo[mbase + r0 + 8];
#pragma unroll
        for (int j = 0; j < 4; j++) {
            const int col = wn + 8 * j + 2 * tg;
            *(float2*)&OutB[(size_t)r0 * NN + col] =
                make_float2(acc[i][j][0] * IS + b0v, acc[i][j][1] * IS + b0v);
            *(float2*)&OutB[(size_t)(r0 + 8) * NN + col] =
                make_float2(acc[i][j][2] * IS + b1v, acc[i][j][3] * IS + b1v);
        }
    }
}

// ---------------------------------------------------------------------------
extern "C" void kernel_launch(void* const* d_in, const int* in_sizes, int n_in,
                              void* d_out, int out_size)
{
    const float* x    = (const float*)d_in[0];
    const float* cp   = (const float*)d_in[1];
    const float* wq   = (const float*)d_in[2];
    const float* bq   = (const float*)d_in[3];
    const float* wkv  = (const float*)d_in[4];
    const float* bkv  = (const float*)d_in[5];
    const float* wo   = (const float*)d_in[6];
    const float* bo   = (const float*)d_in[7];
    float* out = (float*)d_out;

    const int smA = (int)sizeof(SmP<true>);   // ~56.8 KB
    const int smC = (int)sizeof(SmP<false>);  // ~61.4 KB
    cudaFuncSetAttribute(gemm_qkv, cudaFuncAttributeMaxDynamicSharedMemorySize, smA);
    cudaFuncSetAttribute(gemm_ctx, cudaFuncAttributeMaxDynamicSharedMemorySize, smC);
    cudaFuncSetAttribute(gemm_out, cudaFuncAttributeMaxDynamicSharedMemorySize, smA);

    conv_all<<<8288, 256>>>(x, cp, wq, wkv);
    gemm_qkv<<<dim3(32, 6, 8), 256, smA>>>(bq, bkv);
    softmax_all<<<2560, 256>>>();
    gemm_ctx<<<dim3(2, 2, 64), 256, smC>>>();
    gemm_wc<<<dim3(4, 4, 8), 256>>>(wo);
    gemm_out<<<dim3(32, 2, 8), 256, smA>>>(bo, out);
}